// round 2
// baseline (speedup 1.0000x reference)
#include <cuda_runtime.h>
#include <math.h>
#include <float.h>

// Problem constants
#define B_    1024
#define L_    128
#define DIN   130
#define H_    768
#define FEAT_ 49
#define PROJ_ 40
#define NG    3072          // 4*H
#define NATT  384           // 3*L
#define LDA   1184          // row stride of the [v | pad | h | pad] A matrix
#define HOFF  400           // h column offset inside A (float4 aligned)
#define KTOT  1184          // padded K for gates GEMM (multiple of 32)

// ---------------- device scratch (no allocations allowed) ----------------
__device__ float g_va[B_ * LDA];        // A matrix: cols [0,390)=v, [400,1168)=h, pads zero
__device__ float g_c[B_ * H_];          // cell state
__device__ float g_hmax[B_ * H_];       // running max over time of h
__device__ float g_logits[B_ * NATT];
__device__ float g_gates[B_ * NG];
__device__ float g_Wl[H_ * NATT];       // W_att transposed to [K=768][N=384]
__device__ float g_Wcat[KTOT * NG];     // [K=1184][N=3072]: rows 0..389 = W_ih^T, 400..1167 = W_hh^T, rest 0
__device__ float g_bsum[NG];            // b_ih + b_hh

// ---------------- packed f32x2 helpers (FFMA2 pipe) ----------------
__device__ __forceinline__ unsigned long long pk2(float x, float y) {
    unsigned long long r;
    asm("mov.b64 %0, {%1, %2};" : "=l"(r) : "f"(x), "f"(y));
    return r;
}
__device__ __forceinline__ unsigned long long ffma2(unsigned long long a,
                                                    unsigned long long b,
                                                    unsigned long long c) {
    unsigned long long d;
    asm("fma.rn.f32x2 %0, %1, %2, %3;" : "=l"(d) : "l"(a), "l"(b), "l"(c));
    return d;
}
__device__ __forceinline__ float2 upk2(unsigned long long a) {
    float2 f;
    asm("mov.b64 {%0, %1}, %2;" : "=f"(f.x), "=f"(f.y) : "l"(a));
    return f;
}

__device__ __forceinline__ float sigmf(float x) { return 1.0f / (1.0f + expf(-x)); }

// ---------------- init: weight transposes + state init ----------------
__global__ void k_init(const float* __restrict__ W_att, const float* __restrict__ W_ih,
                       const float* __restrict__ W_hh, const float* __restrict__ b_ih,
                       const float* __restrict__ b_hh) {
    int g = blockIdx.x * blockDim.x + threadIdx.x;
    int stride = gridDim.x * blockDim.x;
    // Wl[k][j], j = ks*128 + l  <- W_att[ks][k][l]
    for (int i = g; i < H_ * NATT; i += stride) {
        int k = i / NATT, j = i % NATT;
        int ks = j >> 7, l = j & 127;
        g_Wl[i] = W_att[ks * (H_ * L_) + k * L_ + l];
    }
    // Wcat[r][n]
    for (int i = g; i < KTOT * NG; i += stride) {
        int r = i / NG, n = i % NG;
        float v = 0.0f;
        if (r < 390)                      v = W_ih[n * 390 + r];
        else if (r >= HOFF && r < HOFF + H_) v = W_hh[n * H_ + (r - HOFF)];
        g_Wcat[i] = v;
    }
    for (int i = g; i < NG; i += stride) g_bsum[i] = b_ih[i] + b_hh[i];
    for (int i = g; i < B_ * LDA; i += stride) g_va[i] = 0.0f;
    for (int i = g; i < B_ * H_; i += stride) { g_c[i] = 0.0f; g_hmax[i] = -FLT_MAX; }
}

// ---------------- tiled fp32 GEMM with f32x2 accumulation ----------------
// C[M][N] = A[M][K] @ Bm[K][N] + bias[N], A row stride = LDA, 256 threads/block
template <int BM, int BN, int BK, int TM, int TN, int N, int K>
__global__ void k_gemm(const float* __restrict__ A, const float* __restrict__ Bm,
                       const float* __restrict__ bias, float* __restrict__ C) {
    constexpr int ASTR = BM + 4;
    __shared__ float As[BK * ASTR];   // transposed: As[k][m]
    __shared__ float Bs[BK * BN];
    const int tid = threadIdx.x;
    const int m0 = blockIdx.y * BM;
    const int n0 = blockIdx.x * BN;
    constexpr int TX = BN / TN;
    const int tx = tid % TX, ty = tid / TX;

    unsigned long long acc[TM][TN / 2];
#pragma unroll
    for (int i = 0; i < TM; i++)
#pragma unroll
        for (int j = 0; j < TN / 2; j++) acc[i][j] = 0ull;

    for (int kt = 0; kt < K; kt += BK) {
        // A tile (float4 loads, transposed store)
        for (int i = tid; i < BM * (BK / 4); i += 256) {
            int row = i / (BK / 4), c4 = i % (BK / 4);
            float4 v = *(const float4*)(A + (size_t)(m0 + row) * LDA + kt + c4 * 4);
            As[(c4 * 4 + 0) * ASTR + row] = v.x;
            As[(c4 * 4 + 1) * ASTR + row] = v.y;
            As[(c4 * 4 + 2) * ASTR + row] = v.z;
            As[(c4 * 4 + 3) * ASTR + row] = v.w;
        }
        // B tile
        for (int i = tid; i < BK * (BN / 4); i += 256) {
            int row = i / (BN / 4), c4 = i % (BN / 4);
            *(float4*)&Bs[row * BN + c4 * 4] =
                *(const float4*)(Bm + (size_t)(kt + row) * N + n0 + c4 * 4);
        }
        __syncthreads();
#pragma unroll
        for (int kk = 0; kk < BK; kk++) {
            float ra[TM];
#pragma unroll
            for (int i = 0; i < TM; i++) ra[i] = As[kk * ASTR + ty * TM + i];
            unsigned long long rb[TN / 2];
#pragma unroll
            for (int j = 0; j < TN / 2; j++) {
                float2 bb = *(const float2*)&Bs[kk * BN + tx * TN + 2 * j];
                rb[j] = pk2(bb.x, bb.y);
            }
#pragma unroll
            for (int i = 0; i < TM; i++) {
                unsigned long long a2 = pk2(ra[i], ra[i]);
#pragma unroll
                for (int j = 0; j < TN / 2; j++) acc[i][j] = ffma2(a2, rb[j], acc[i][j]);
            }
        }
        __syncthreads();
    }
#pragma unroll
    for (int i = 0; i < TM; i++) {
        int m = m0 + ty * TM + i;
#pragma unroll
        for (int j = 0; j < TN / 2; j++) {
            float2 r = upk2(acc[i][j]);
            int n = n0 + tx * TN + 2 * j;
            C[(size_t)m * N + n]     = r.x + bias[n];
            C[(size_t)m * N + n + 1] = r.y + bias[n + 1];
        }
    }
}

// ---------------- fused softmax + attention pooling ----------------
// one block per b, 416 threads (384 used for softmax, 390 for v)
__global__ void k_attn(const float* __restrict__ X) {
    __shared__ float alp[NATT];
    __shared__ float xs[16 * DIN];
    __shared__ float red[16];
    const int b = blockIdx.x;
    const int tid = threadIdx.x;
    for (int i = tid; i < NATT; i += 416) alp[i] = g_logits[b * NATT + i];
    __syncthreads();

    const int wid = tid >> 5, lane = tid & 31;
    float xv = (tid < NATT) ? alp[tid] : -FLT_MAX;
    // row max over 128 (4 warps per row)
    float m = xv;
#pragma unroll
    for (int off = 16; off; off >>= 1) m = fmaxf(m, __shfl_xor_sync(0xffffffffu, m, off));
    if (lane == 0) red[wid] = m;
    __syncthreads();
    if (tid < NATT) {
        int k4 = (tid >> 7) << 2;
        float rm = fmaxf(fmaxf(red[k4], red[k4 + 1]), fmaxf(red[k4 + 2], red[k4 + 3]));
        xv = expf(xv - rm);
    } else {
        xv = 0.0f;
    }
    __syncthreads();
    float s = xv;
#pragma unroll
    for (int off = 16; off; off >>= 1) s += __shfl_xor_sync(0xffffffffu, s, off);
    if (lane == 0) red[wid] = s;
    __syncthreads();
    if (tid < NATT) {
        int k4 = (tid >> 7) << 2;
        float rs = red[k4] + red[k4 + 1] + red[k4 + 2] + red[k4 + 3];
        alp[tid] = xv / rs;
    }
    __syncthreads();

    // v[b][k*130+d] = sum_l alp[k][l] * X[b][l][d], staged 16 rows of X at a time
    float acc = 0.0f;
    const int k = tid / DIN, d = tid - k * DIN;   // valid for tid < 390
    const float* Xb = X + (size_t)b * (L_ * DIN);
    for (int lc = 0; lc < L_; lc += 16) {
        for (int i = tid; i < 16 * DIN; i += 416) xs[i] = Xb[lc * DIN + i];
        __syncthreads();
        if (tid < 390) {
#pragma unroll
            for (int l = 0; l < 16; l++) acc += alp[k * L_ + lc + l] * xs[l * DIN + d];
        }
        __syncthreads();
    }
    if (tid < 390) g_va[(size_t)b * LDA + tid] = acc;
}

// ---------------- LSTM pointwise cell ----------------
__global__ void k_cell() {
    int idx = blockIdx.x * blockDim.x + threadIdx.x;
    if (idx >= B_ * H_) return;
    int b = idx / H_, hh = idx - b * H_;
    const float* g = g_gates + (size_t)b * NG;
    float ig = sigmf(g[hh]);
    float fg = sigmf(g[H_ + hh]);
    float gg = tanhf(g[2 * H_ + hh]);
    float og = sigmf(g[3 * H_ + hh]);
    float c = fg * g_c[idx] + ig * gg;
    float h = og * tanhf(c);
    g_c[idx] = c;
    g_va[(size_t)b * LDA + HOFF + hh] = h;       // h feeds next step's GEMMs
    g_hmax[idx] = fmaxf(g_hmax[idx], h);
}

// ---------------- fused tail: Dense1 + AttFeat + Dense2 ----------------
__global__ void k_tail(const float* __restrict__ Fe, const float* __restrict__ W_d1,
                       const float* __restrict__ b_d1, const float* __restrict__ W_r,
                       const float* __restrict__ b_r, const float* __restrict__ W_a,
                       const float* __restrict__ W_d2, const float* __restrict__ b_d2,
                       float* __restrict__ out) {
    __shared__ float hs[H_];
    __shared__ float yb[FEAT_];
    __shared__ float r1[PROJ_], r2[PROJ_], sb[PROJ_];
    __shared__ float aw[2];
    const int b = blockIdx.x, tid = threadIdx.x;   // 64 threads
    for (int i = tid; i < H_; i += 64) hs[i] = g_hmax[b * H_ + i];
    __syncthreads();
    if (tid < FEAT_) {
        float a = b_d1[tid];
        const float* w = W_d1 + tid * H_;
        for (int k2 = 0; k2 < H_; k2++) a += hs[k2] * w[k2];
        yb[tid] = fmaxf(a, 0.0f);
    }
    __syncthreads();
    if (tid < PROJ_) {
        float a = b_r[tid], a2 = b_r[tid];
        const float* w = W_r + tid * FEAT_;
        const float* fe = Fe + b * FEAT_;
        for (int q = 0; q < FEAT_; q++) { a += yb[q] * w[q]; a2 += fe[q] * w[q]; }
        r1[tid] = a  > 0.0f ? a  : 0.01f * a;
        r2[tid] = a2 > 0.0f ? a2 : 0.01f * a2;
    }
    __syncthreads();
    if (tid == 0) {
        float s1 = 0.0f, s2 = 0.0f;
        for (int p = 0; p < PROJ_; p++) { s1 += tanhf(r1[p]) * W_a[p]; s2 += tanhf(r2[p]) * W_a[p]; }
        float mx = fmaxf(s1, s2);
        float e1 = expf(s1 - mx), e2 = expf(s2 - mx);
        float inv = 1.0f / (e1 + e2);
        aw[0] = e1 * inv; aw[1] = e2 * inv;
    }
    __syncthreads();
    if (tid < PROJ_) sb[tid] = fmaxf(aw[0] * r1[tid] + aw[1] * r2[tid], 0.0f);
    __syncthreads();
    if (tid < 2) {
        float a = b_d2[tid];
        const float* w = W_d2 + tid * PROJ_;
        for (int p = 0; p < PROJ_; p++) a += sb[p] * w[p];
        out[b * 2 + tid] = a;
    }
}

// ---------------- launch ----------------
extern "C" void kernel_launch(void* const* d_in, const int* in_sizes, int n_in,
                              void* d_out, int out_size) {
    const float* X     = (const float*)d_in[0];
    const float* Fe    = (const float*)d_in[1];
    const float* W_att = (const float*)d_in[2];
    const float* b_att = (const float*)d_in[3];
    const float* W_ih  = (const float*)d_in[4];
    const float* W_hh  = (const float*)d_in[5];
    const float* b_ih  = (const float*)d_in[6];
    const float* b_hh  = (const float*)d_in[7];
    const float* W_d1  = (const float*)d_in[8];
    const float* b_d1  = (const float*)d_in[9];
    const float* W_r   = (const float*)d_in[10];
    const float* b_r   = (const float*)d_in[11];
    const float* W_a   = (const float*)d_in[12];
    const float* W_d2  = (const float*)d_in[13];
    const float* b_d2  = (const float*)d_in[14];
    float* out = (float*)d_out;

    float *va, *Wl, *Wcat, *bsum, *logits, *gates;
    cudaGetSymbolAddress((void**)&va,     g_va);
    cudaGetSymbolAddress((void**)&Wl,     g_Wl);
    cudaGetSymbolAddress((void**)&Wcat,   g_Wcat);
    cudaGetSymbolAddress((void**)&bsum,   g_bsum);
    cudaGetSymbolAddress((void**)&logits, g_logits);
    cudaGetSymbolAddress((void**)&gates,  g_gates);

    k_init<<<2048, 256>>>(W_att, W_ih, W_hh, b_ih, b_hh);

    for (int t = 0; t < L_; t++) {
        // logits[1024,384] = h[1024,768] @ Wl[768,384] + b_att
        k_gemm<32, 64, 32, 2, 4, NATT, H_>
            <<<dim3(NATT / 64, B_ / 32), 256>>>(va + HOFF, Wl, b_att, logits);
        // softmax + v (writes v section of A)
        k_attn<<<B_, 416>>>(X);
        // gates[1024,3072] = [v|h][1024,1184] @ Wcat[1184,3072] + (b_ih+b_hh)
        k_gemm<64, 64, 32, 4, 4, NG, KTOT>
            <<<dim3(NG / 64, B_ / 64), 256>>>(va, Wcat, bsum, gates);
        // LSTM cell + running max + write h back into A
        k_cell<<<(B_ * H_ + 255) / 256, 256>>>();
    }

    k_tail<<<B_, 64>>>(Fe, W_d1, b_d1, W_r, b_r, W_a, W_d2, b_d2, out);
}

// round 4
// speedup vs baseline: 1.9257x; 1.9257x over previous
#include <cuda_runtime.h>
#include <cuda_bf16.h>
#include <math.h>
#include <float.h>
#include <stdint.h>

#define B_    1024
#define L_    128
#define DIN   130
#define H_    768
#define FEAT_ 49
#define PROJ_ 40
#define NG    3072          // 4*H
#define NATT  384           // 3*L
#define KTOT  1216          // padded K: [0,390)=v, [400,1168)=h, rest 0
#define HOFF  400
#define NCH_G 19            // KTOT/64
#define NCH_L 12            // 768/64

typedef __nv_bfloat16 bf16;

// ---------------- device scratch ----------------
__device__ bf16 g_Ahi0[B_*KTOT], g_Alo0[B_*KTOT];   // ping-pong A (hi/lo split)
__device__ bf16 g_Ahi1[B_*KTOT], g_Alo1[B_*KTOT];
__device__ bf16 g_Whi[NG*KTOT],  g_Wlo[NG*KTOT];    // gates W^T [n_perm][k]
__device__ bf16 g_Lhi[NATT*H_],  g_Llo[NATT*H_];    // logits W^T [n][k]
__device__ float g_bsum[NG];                        // b_ih+b_hh, permuted
__device__ float g_c[B_*H_], g_hmax[B_*H_];         // [b][j]
__device__ float g_logits[B_*NATT];

// ---------------- helpers ----------------
__device__ __forceinline__ uint32_t smem_u32(const void* p) {
    return (uint32_t)__cvta_generic_to_shared(p);
}
__device__ __forceinline__ void cpa16(uint32_t dst, const void* src) {
    asm volatile("cp.async.cg.shared.global [%0], [%1], 16;"
                 :: "r"(dst), "l"(__cvta_generic_to_global(src)));
}
#define CPA_COMMIT() asm volatile("cp.async.commit_group;")

#define LDSM4(r, a) \
    asm volatile("ldmatrix.sync.aligned.m8n8.x4.shared.b16 {%0,%1,%2,%3}, [%4];" \
        : "=r"((r)[0]), "=r"((r)[1]), "=r"((r)[2]), "=r"((r)[3]) : "r"(a))

__device__ __forceinline__ void mma16816(float* d, const uint32_t* a, const uint32_t* b) {
    asm volatile("mma.sync.aligned.m16n8k16.row.col.f32.bf16.bf16.f32 "
        "{%0,%1,%2,%3}, {%4,%5,%6,%7}, {%8,%9}, {%0,%1,%2,%3};"
        : "+f"(d[0]), "+f"(d[1]), "+f"(d[2]), "+f"(d[3])
        : "r"(a[0]), "r"(a[1]), "r"(a[2]), "r"(a[3]), "r"(b[0]), "r"(b[1]));
}

__device__ __forceinline__ float sigmf(float x) { return 1.0f / (1.0f + __expf(-x)); }

// ---------------- init: bf16 hi/lo weight builds, gate-permuted columns ----------------
// permuted col n = 16q + 8h + 2a + e  <->  gate (2h+e) of hidden j = 4q + a
__global__ void k_init(const float* __restrict__ W_att, const float* __restrict__ W_ih,
                       const float* __restrict__ W_hh, const float* __restrict__ b_ih,
                       const float* __restrict__ b_hh) {
    long g = (long)blockIdx.x * blockDim.x + threadIdx.x;
    long stride = (long)gridDim.x * blockDim.x;
    for (long i = g; i < (long)NG * KTOT; i += stride) {
        int n = (int)(i / KTOT), k = (int)(i % KTOT);
        int q = n >> 4, r = n & 15;
        int gate = ((r >> 3) << 1) | (r & 1);
        int j = (q << 2) + ((r & 7) >> 1);
        int srow = gate * H_ + j;
        float w = 0.0f;
        if (k < 390)                         w = W_ih[(size_t)srow * 390 + k];
        else if (k >= HOFF && k < HOFF + H_) w = W_hh[(size_t)srow * H_ + (k - HOFF)];
        bf16 hi = __float2bfloat16(w);
        g_Whi[i] = hi;
        g_Wlo[i] = __float2bfloat16(w - __bfloat162float(hi));
    }
    for (long i = g; i < (long)NATT * H_; i += stride) {
        int n = (int)(i / H_), k = (int)(i % H_);
        int ks = n >> 7, l = n & 127;
        float w = W_att[(size_t)ks * (H_ * L_) + (size_t)k * L_ + l];
        bf16 hi = __float2bfloat16(w);
        g_Lhi[i] = hi;
        g_Llo[i] = __float2bfloat16(w - __bfloat162float(hi));
    }
    for (long i = g; i < NG; i += stride) {
        int n = (int)i;
        int q = n >> 4, r = n & 15;
        int gate = ((r >> 3) << 1) | (r & 1);
        int j = (q << 2) + ((r & 7) >> 1);
        g_bsum[i] = b_ih[gate * H_ + j] + b_hh[gate * H_ + j];
    }
    bf16 z = __float2bfloat16(0.0f);
    for (long i = g; i < (long)B_ * KTOT; i += stride) {
        g_Ahi0[i] = z; g_Alo0[i] = z; g_Ahi1[i] = z; g_Alo1[i] = z;
    }
    for (long i = g; i < (long)B_ * H_; i += stride) { g_c[i] = 0.0f; g_hmax[i] = -FLT_MAX; }
}

// ---------------- stage loader: global -> smem (4 matrices: Ahi,Alo,Bhi,Blo) ----------------
template <int BM, int BN, int NT, int BSTR>
__device__ __forceinline__ void load_stage(int s, uint32_t smbase, int tid,
                                           const bf16* __restrict__ Ah,
                                           const bf16* __restrict__ Al,
                                           const bf16* __restrict__ Bh,
                                           const bf16* __restrict__ Bl) {
    constexpr uint32_t STAGE_B = (BM + BN) * 2u * 144u;
    uint32_t st   = smbase + (uint32_t)(s & 1) * STAGE_B;
    uint32_t stAl = st + BM * 144u;
    uint32_t stBh = st + 2u * BM * 144u;
    uint32_t stBl = stBh + BN * 144u;
    const int k0 = s * 64;
#pragma unroll
    for (int r = 0; r < (BM * 8) / NT; r++) {
        int i = tid + r * NT, row = i >> 3, seg = i & 7;
        uint32_t off = row * 144 + seg * 16;
        size_t go = (size_t)row * KTOT + k0 + seg * 8;
        cpa16(st + off,   Ah + go);
        cpa16(stAl + off, Al + go);
    }
#pragma unroll
    for (int r = 0; r < (BN * 8) / NT; r++) {
        int i = tid + r * NT, row = i >> 3, seg = i & 7;
        uint32_t off = row * 144 + seg * 16;
        size_t go = (size_t)row * BSTR + k0 + seg * 8;
        cpa16(stBh + off, Bh + go);
        cpa16(stBl + off, Bl + go);
    }
    CPA_COMMIT();
}

// ---------------- mma.sync GEMM, hi/lo 3-product, fused epilogue ----------------
// GATES=true : epilogue = LSTM cell, writes h (hi/lo) into write A buffer
// GATES=false: epilogue = logits + bias
template <int BM, int BN, int WM, bool GATES, int BSTR, int NCH>
__global__ void __launch_bounds__((BM / WM) * (BN / 32) * 32, 1)
k_mma(const bf16* __restrict__ gAhi, const bf16* __restrict__ gAlo,
      bf16* __restrict__ wAhi, bf16* __restrict__ wAlo,
      const bf16* __restrict__ gBhi, const bf16* __restrict__ gBlo,
      const float* __restrict__ bias) {
    constexpr int NWX = BN / 32, NWY = BM / WM, NT = NWX * NWY * 32;
    constexpr int MT = WM / 16;
    extern __shared__ __align__(128) bf16 sm[];
    __shared__ float s_bias[BN];

    const int tid = threadIdx.x, w = tid >> 5, lane = tid & 31;
    const int wx = w % NWX, wy = w / NWX;
    const int m0 = blockIdx.y * BM, n0 = blockIdx.x * BN;
    const uint32_t smb = smem_u32(sm);

    for (int i = tid; i < BN; i += NT) s_bias[i] = bias[n0 + i];

    const bf16* Ah = gAhi + (size_t)m0 * KTOT;
    const bf16* Al = gAlo + (size_t)m0 * KTOT;
    const bf16* Bh = gBhi + (size_t)n0 * BSTR;
    const bf16* Bl = gBlo + (size_t)n0 * BSTR;

    float acc[MT][4][4];
#pragma unroll
    for (int i = 0; i < MT; i++)
#pragma unroll
        for (int j = 0; j < 4; j++)
#pragma unroll
            for (int k = 0; k < 4; k++) acc[i][j][k] = 0.0f;

    load_stage<BM, BN, NT, BSTR>(0, smb, tid, Ah, Al, Bh, Bl);

    for (int s = 0; s < NCH; s++) {
        if (s + 1 < NCH) {
            load_stage<BM, BN, NT, BSTR>(s + 1, smb, tid, Ah, Al, Bh, Bl);
            asm volatile("cp.async.wait_group 1;");
        } else {
            asm volatile("cp.async.wait_group 0;");
        }
        __syncthreads();

        constexpr uint32_t STAGE_B = (BM + BN) * 2u * 144u;
        uint32_t st   = smb + (uint32_t)(s & 1) * STAGE_B;
        uint32_t stBh = st + 2u * BM * 144u;
#pragma unroll
        for (int ks = 0; ks < 4; ks++) {
            const int kk = ks * 16;
            uint32_t ah[MT][4], alr[MT][4];
#pragma unroll
            for (int mt = 0; mt < MT; mt++) {
                uint32_t addr = st + (uint32_t)((wy * WM + mt * 16 + (lane & 15)) * 144
                               + (kk + ((lane >> 4) << 3)) * 2);
                LDSM4(ah[mt], addr);
                LDSM4(alr[mt], addr + BM * 144u);
            }
            uint32_t bh[8], bl[8];
#pragma unroll
            for (int nb = 0; nb < 2; nb++) {
                int gg = lane >> 3;
                uint32_t addr = stBh + (uint32_t)((wx * 32 + nb * 16 + ((gg >> 1) << 3)
                               + (lane & 7)) * 144 + (kk + ((gg & 1) << 3)) * 2);
                LDSM4(bh + nb * 4, addr);
                LDSM4(bl + nb * 4, addr + BN * 144u);
            }
#pragma unroll
            for (int mt = 0; mt < MT; mt++)
#pragma unroll
                for (int nt = 0; nt < 4; nt++) {
                    const uint32_t* ph = bh + (nt >> 1) * 4 + (nt & 1) * 2;
                    const uint32_t* pl = bl + (nt >> 1) * 4 + (nt & 1) * 2;
                    mma16816(acc[mt][nt], ah[mt],  ph);
                    mma16816(acc[mt][nt], ah[mt],  pl);
                    mma16816(acc[mt][nt], alr[mt], ph);
                }
        }
        __syncthreads();
    }

    const int a_ = lane & 3, rl = lane >> 2;
    if constexpr (GATES) {
#pragma unroll
        for (int mt = 0; mt < MT; mt++)
#pragma unroll
            for (int p = 0; p < 2; p++) {
                const int colb = wx * 32 + p * 16;
                const float bi = s_bias[colb + 2 * a_];
                const float bf = s_bias[colb + 2 * a_ + 1];
                const float bg = s_bias[colb + 8 + 2 * a_];
                const float bo = s_bias[colb + 8 + 2 * a_ + 1];
                const int j = ((n0 + colb) >> 2) + a_;
#pragma unroll
                for (int rh = 0; rh < 2; rh++) {
                    float iv = acc[mt][2 * p][2 * rh]     + bi;
                    float fv = acc[mt][2 * p][2 * rh + 1] + bf;
                    float gv = acc[mt][2 * p + 1][2 * rh]     + bg;
                    float ov = acc[mt][2 * p + 1][2 * rh + 1] + bo;
                    int b = m0 + wy * WM + mt * 16 + rh * 8 + rl;
                    size_t cidx = (size_t)b * H_ + j;
                    float c = sigmf(fv) * g_c[cidx] + sigmf(iv) * tanhf(gv);
                    float h = sigmf(ov) * tanhf(c);
                    g_c[cidx] = c;
                    g_hmax[cidx] = fmaxf(g_hmax[cidx], h);
                    bf16 hh = __float2bfloat16(h);
                    size_t widx = (size_t)b * KTOT + HOFF + j;
                    wAhi[widx] = hh;
                    wAlo[widx] = __float2bfloat16(h - __bfloat162float(hh));
                }
            }
    } else {
#pragma unroll
        for (int mt = 0; mt < MT; mt++)
#pragma unroll
            for (int nt = 0; nt < 4; nt++) {
                const int lc = wx * 32 + nt * 8 + 2 * a_;
#pragma unroll
                for (int rh = 0; rh < 2; rh++) {
                    int row = m0 + wy * WM + mt * 16 + rh * 8 + rl;
                    float2 v;
                    v.x = acc[mt][nt][2 * rh]     + s_bias[lc];
                    v.y = acc[mt][nt][2 * rh + 1] + s_bias[lc + 1];
                    *(float2*)&g_logits[(size_t)row * NATT + n0 + lc] = v;
                }
            }
    }
}

// ---------------- fused softmax + attention pooling (writes v as bf16 hi/lo) ----------------
__global__ void k_attn(const float* __restrict__ X, bf16* __restrict__ wHi,
                       bf16* __restrict__ wLo) {
    __shared__ float alp[NATT];
    __shared__ float xs[16 * DIN];
    __shared__ float red[16];
    const int b = blockIdx.x;
    const int tid = threadIdx.x;
    for (int i = tid; i < NATT; i += 416) alp[i] = g_logits[b * NATT + i];
    __syncthreads();

    const int wid = tid >> 5, lane = tid & 31;
    float xv = (tid < NATT) ? alp[tid] : -FLT_MAX;
    float m = xv;
#pragma unroll
    for (int off = 16; off; off >>= 1) m = fmaxf(m, __shfl_xor_sync(0xffffffffu, m, off));
    if (lane == 0) red[wid] = m;
    __syncthreads();
    if (tid < NATT) {
        int k4 = (tid >> 7) << 2;
        float rm = fmaxf(fmaxf(red[k4], red[k4 + 1]), fmaxf(red[k4 + 2], red[k4 + 3]));
        xv = expf(xv - rm);
    } else xv = 0.0f;
    __syncthreads();
    float s = xv;
#pragma unroll
    for (int off = 16; off; off >>= 1) s += __shfl_xor_sync(0xffffffffu, s, off);
    if (lane == 0) red[wid] = s;
    __syncthreads();
    if (tid < NATT) {
        int k4 = (tid >> 7) << 2;
        float rs = red[k4] + red[k4 + 1] + red[k4 + 2] + red[k4 + 3];
        alp[tid] = xv / rs;
    }
    __syncthreads();

    float acc = 0.0f;
    const int k = tid / DIN, d = tid - k * DIN;
    const float* Xb = X + (size_t)b * (L_ * DIN);
    for (int lc = 0; lc < L_; lc += 16) {
        for (int i = tid; i < 16 * DIN; i += 416) xs[i] = Xb[lc * DIN + i];
        __syncthreads();
        if (tid < 390) {
#pragma unroll
            for (int l = 0; l < 16; l++) acc += alp[k * L_ + lc + l] * xs[l * DIN + d];
        }
        __syncthreads();
    }
    if (tid < 390) {
        bf16 hi = __float2bfloat16(acc);
        wHi[(size_t)b * KTOT + tid] = hi;
        wLo[(size_t)b * KTOT + tid] = __float2bfloat16(acc - __bfloat162float(hi));
    }
}

// ---------------- fused tail ----------------
__global__ void k_tail(const float* __restrict__ Fe, const float* __restrict__ W_d1,
                       const float* __restrict__ b_d1, const float* __restrict__ W_r,
                       const float* __restrict__ b_r, const float* __restrict__ W_a,
                       const float* __restrict__ W_d2, const float* __restrict__ b_d2,
                       float* __restrict__ out) {
    __shared__ float hs[H_];
    __shared__ float yb[FEAT_];
    __shared__ float r1[PROJ_], r2[PROJ_], sb[PROJ_];
    __shared__ float aw[2];
    const int b = blockIdx.x, tid = threadIdx.x;   // 64 threads
    for (int i = tid; i < H_; i += 64) hs[i] = g_hmax[(size_t)b * H_ + i];
    __syncthreads();
    if (tid < FEAT_) {
        float a = b_d1[tid];
        const float* w = W_d1 + tid * H_;
        for (int k2 = 0; k2 < H_; k2++) a += hs[k2] * w[k2];
        yb[tid] = fmaxf(a, 0.0f);
    }
    __syncthreads();
    if (tid < PROJ_) {
        float a = b_r[tid], a2 = b_r[tid];
        const float* w = W_r + tid * FEAT_;
        const float* fe = Fe + b * FEAT_;
        for (int q = 0; q < FEAT_; q++) { a += yb[q] * w[q]; a2 += fe[q] * w[q]; }
        r1[tid] = a  > 0.0f ? a  : 0.01f * a;
        r2[tid] = a2 > 0.0f ? a2 : 0.01f * a2;
    }
    __syncthreads();
    if (tid == 0) {
        float s1 = 0.0f, s2 = 0.0f;
        for (int p = 0; p < PROJ_; p++) { s1 += tanhf(r1[p]) * W_a[p]; s2 += tanhf(r2[p]) * W_a[p]; }
        float mx = fmaxf(s1, s2);
        float e1 = expf(s1 - mx), e2 = expf(s2 - mx);
        float inv = 1.0f / (e1 + e2);
        aw[0] = e1 * inv; aw[1] = e2 * inv;
    }
    __syncthreads();
    if (tid < PROJ_) sb[tid] = fmaxf(aw[0] * r1[tid] + aw[1] * r2[tid], 0.0f);
    __syncthreads();
    if (tid < 2) {
        float a = b_d2[tid];
        const float* w = W_d2 + tid * PROJ_;
        for (int p = 0; p < PROJ_; p++) a += sb[p] * w[p];
        out[b * 2 + tid] = a;
    }
}

// ---------------- launch ----------------
extern "C" void kernel_launch(void* const* d_in, const int* in_sizes, int n_in,
                              void* d_out, int out_size) {
    const float* X     = (const float*)d_in[0];
    const float* Fe    = (const float*)d_in[1];
    const float* W_att = (const float*)d_in[2];
    const float* b_att = (const float*)d_in[3];
    const float* W_ih  = (const float*)d_in[4];
    const float* W_hh  = (const float*)d_in[5];
    const float* b_ih  = (const float*)d_in[6];
    const float* b_hh  = (const float*)d_in[7];
    const float* W_d1  = (const float*)d_in[8];
    const float* b_d1  = (const float*)d_in[9];
    const float* W_r   = (const float*)d_in[10];
    const float* b_r   = (const float*)d_in[11];
    const float* W_a   = (const float*)d_in[12];
    const float* W_d2  = (const float*)d_in[13];
    const float* b_d2  = (const float*)d_in[14];
    float* out = (float*)d_out;

    bf16 *Ah0, *Al0, *Ah1, *Al1, *Whi, *Wlo, *Lhi, *Llo;
    float *bsum;
    cudaGetSymbolAddress((void**)&Ah0, g_Ahi0);
    cudaGetSymbolAddress((void**)&Al0, g_Alo0);
    cudaGetSymbolAddress((void**)&Ah1, g_Ahi1);
    cudaGetSymbolAddress((void**)&Al1, g_Alo1);
    cudaGetSymbolAddress((void**)&Whi, g_Whi);
    cudaGetSymbolAddress((void**)&Wlo, g_Wlo);
    cudaGetSymbolAddress((void**)&Lhi, g_Lhi);
    cudaGetSymbolAddress((void**)&Llo, g_Llo);
    cudaGetSymbolAddress((void**)&bsum, g_bsum);

    constexpr int DSMEM_G = 2 * (128 + 128) * 2 * 144;   // 147456 B
    constexpr int DSMEM_L = 2 * (64 + 64) * 2 * 144;     //  73728 B
    cudaFuncSetAttribute((const void*)k_mma<128, 128, 64, true,  KTOT, NCH_G>,
                         cudaFuncAttributeMaxDynamicSharedMemorySize, DSMEM_G);
    cudaFuncSetAttribute((const void*)k_mma<64, 64, 32, false, H_,  NCH_L>,
                         cudaFuncAttributeMaxDynamicSharedMemorySize, DSMEM_L);

    k_init<<<2048, 256>>>(W_att, W_ih, W_hh, b_ih, b_hh);

    for (int t = 0; t < L_; t++) {
        bf16* rdHi = (t & 1) ? Ah1 : Ah0;
        bf16* rdLo = (t & 1) ? Al1 : Al0;
        bf16* wrHi = (t & 1) ? Ah0 : Ah1;
        bf16* wrLo = (t & 1) ? Al0 : Al1;
        // logits[1024,384] = h @ Wl + b_att
        k_mma<64, 64, 32, false, H_, NCH_L><<<dim3(NATT / 64, B_ / 64), 128, DSMEM_L>>>(
            rdHi + HOFF, rdLo + HOFF, nullptr, nullptr, Lhi, Llo, b_att);
        // softmax + attention pooling -> v into rd buffer
        k_attn<<<B_, 416>>>(X, rdHi, rdLo);
        // gates = [v|h] @ Wcat + bsum, fused LSTM cell -> h into wr buffer
        k_mma<128, 128, 64, true, KTOT, NCH_G><<<dim3(NG / 128, B_ / 128), 256, DSMEM_G>>>(
            rdHi, rdLo, wrHi, wrLo, Whi, Wlo, bsum);
    }

    k_tail<<<B_, 64>>>(Fe, W_d1, b_d1, W_r, b_r, W_a, W_d2, b_d2, out);
}

// round 5
// speedup vs baseline: 1.9703x; 1.0232x over previous
#include <cuda_runtime.h>
#include <cuda_bf16.h>
#include <math.h>
#include <float.h>
#include <stdint.h>

#define B_    1024
#define L_    128
#define DIN   130
#define H_    768
#define FEAT_ 49
#define PROJ_ 40
#define NG    3072          // 4*H
#define NATT  384           // 3*L
#define KTOT  1216          // padded K: [0,390)=v, [400,1168)=h, rest 0
#define HOFF  400
#define NCH_G 19            // KTOT/64
#define NCH_L 12            // 768/64

typedef __nv_bfloat16 bf16;

// ---------------- device scratch ----------------
__device__ bf16 g_Ahi0[B_*KTOT], g_Alo0[B_*KTOT];   // ping-pong A (hi/lo split)
__device__ bf16 g_Ahi1[B_*KTOT], g_Alo1[B_*KTOT];
__device__ bf16 g_Whi[NG*KTOT],  g_Wlo[NG*KTOT];    // gates W^T [n_perm][k]
__device__ bf16 g_Lhi[NATT*H_],  g_Llo[NATT*H_];    // logits W^T [n][k]
__device__ float g_bsum[NG];                        // b_ih+b_hh, permuted
__device__ float g_c[B_*H_], g_hmax[B_*H_];         // [b][j]
__device__ float g_logits[B_*NATT];

// ---------------- helpers ----------------
__device__ __forceinline__ uint32_t smem_u32(const void* p) {
    return (uint32_t)__cvta_generic_to_shared(p);
}
__device__ __forceinline__ void cpa16(uint32_t dst, const void* src) {
    asm volatile("cp.async.cg.shared.global [%0], [%1], 16;"
                 :: "r"(dst), "l"(__cvta_generic_to_global(src)));
}
#define CPA_COMMIT() asm volatile("cp.async.commit_group;")

#define LDSM4(r, a) \
    asm volatile("ldmatrix.sync.aligned.m8n8.x4.shared.b16 {%0,%1,%2,%3}, [%4];" \
        : "=r"((r)[0]), "=r"((r)[1]), "=r"((r)[2]), "=r"((r)[3]) : "r"(a))

__device__ __forceinline__ void mma16816(float* d, const uint32_t* a, const uint32_t* b) {
    asm volatile("mma.sync.aligned.m16n8k16.row.col.f32.bf16.bf16.f32 "
        "{%0,%1,%2,%3}, {%4,%5,%6,%7}, {%8,%9}, {%0,%1,%2,%3};"
        : "+f"(d[0]), "+f"(d[1]), "+f"(d[2]), "+f"(d[3])
        : "r"(a[0]), "r"(a[1]), "r"(a[2]), "r"(a[3]), "r"(b[0]), "r"(b[1]));
}

__device__ __forceinline__ float sigmf(float x) { return 1.0f / (1.0f + __expf(-x)); }

// ---------------- init: bf16 hi/lo weight builds, gate-permuted columns ----------------
// permuted col n = 16q + 8h + 2a + e  <->  gate (2h+e) of hidden j = 4q + a
__global__ void k_init(const float* __restrict__ W_att, const float* __restrict__ W_ih,
                       const float* __restrict__ W_hh, const float* __restrict__ b_ih,
                       const float* __restrict__ b_hh) {
    long g = (long)blockIdx.x * blockDim.x + threadIdx.x;
    long stride = (long)gridDim.x * blockDim.x;
    for (long i = g; i < (long)NG * KTOT; i += stride) {
        int n = (int)(i / KTOT), k = (int)(i % KTOT);
        int q = n >> 4, r = n & 15;
        int gate = ((r >> 3) << 1) | (r & 1);
        int j = (q << 2) + ((r & 7) >> 1);
        int srow = gate * H_ + j;
        float w = 0.0f;
        if (k < 390)                         w = W_ih[(size_t)srow * 390 + k];
        else if (k >= HOFF && k < HOFF + H_) w = W_hh[(size_t)srow * H_ + (k - HOFF)];
        bf16 hi = __float2bfloat16(w);
        g_Whi[i] = hi;
        g_Wlo[i] = __float2bfloat16(w - __bfloat162float(hi));
    }
    for (long i = g; i < (long)NATT * H_; i += stride) {
        int n = (int)(i / H_), k = (int)(i % H_);
        int ks = n >> 7, l = n & 127;
        float w = W_att[(size_t)ks * (H_ * L_) + (size_t)k * L_ + l];
        bf16 hi = __float2bfloat16(w);
        g_Lhi[i] = hi;
        g_Llo[i] = __float2bfloat16(w - __bfloat162float(hi));
    }
    for (long i = g; i < NG; i += stride) {
        int n = (int)i;
        int q = n >> 4, r = n & 15;
        int gate = ((r >> 3) << 1) | (r & 1);
        int j = (q << 2) + ((r & 7) >> 1);
        g_bsum[i] = b_ih[gate * H_ + j] + b_hh[gate * H_ + j];
    }
    bf16 z = __float2bfloat16(0.0f);
    for (long i = g; i < (long)B_ * KTOT; i += stride) {
        g_Ahi0[i] = z; g_Alo0[i] = z; g_Ahi1[i] = z; g_Alo1[i] = z;
    }
    for (long i = g; i < (long)B_ * H_; i += stride) { g_c[i] = 0.0f; g_hmax[i] = -FLT_MAX; }
}

// ---------------- stage loader: global -> smem (4 matrices: Ahi,Alo,Bhi,Blo) ----------------
template <int BM, int BN, int NT, int BSTR>
__device__ __forceinline__ void load_stage(int s, uint32_t smbase, int tid,
                                           const bf16* __restrict__ Ah,
                                           const bf16* __restrict__ Al,
                                           const bf16* __restrict__ Bh,
                                           const bf16* __restrict__ Bl) {
    constexpr uint32_t STAGE_B = (BM + BN) * 2u * 144u;
    uint32_t st   = smbase + (uint32_t)(s & 1) * STAGE_B;
    uint32_t stAl = st + BM * 144u;
    uint32_t stBh = st + 2u * BM * 144u;
    uint32_t stBl = stBh + BN * 144u;
    const int k0 = s * 64;
#pragma unroll
    for (int r = 0; r < (BM * 8) / NT; r++) {
        int i = tid + r * NT, row = i >> 3, seg = i & 7;
        uint32_t off = row * 144 + seg * 16;
        size_t go = (size_t)row * KTOT + k0 + seg * 8;
        cpa16(st + off,   Ah + go);
        cpa16(stAl + off, Al + go);
    }
#pragma unroll
    for (int r = 0; r < (BN * 8) / NT; r++) {
        int i = tid + r * NT, row = i >> 3, seg = i & 7;
        uint32_t off = row * 144 + seg * 16;
        size_t go = (size_t)row * BSTR + k0 + seg * 8;
        cpa16(stBh + off, Bh + go);
        cpa16(stBl + off, Bl + go);
    }
    CPA_COMMIT();
}

// ---------------- mma.sync GEMM, hi/lo 3-product, fused epilogue ----------------
// GATES=true : epilogue = LSTM cell, writes h (hi/lo) into write A buffer
// GATES=false: epilogue = logits + bias
template <int BM, int BN, int WM, bool GATES, int BSTR, int NCH>
__global__ void __launch_bounds__((BM / WM) * (BN / 32) * 32, 1)
k_mma(const bf16* __restrict__ gAhi, const bf16* __restrict__ gAlo,
      bf16* __restrict__ wAhi, bf16* __restrict__ wAlo,
      const bf16* __restrict__ gBhi, const bf16* __restrict__ gBlo,
      const float* __restrict__ bias) {
    constexpr int NWX = BN / 32, NWY = BM / WM, NT = NWX * NWY * 32;
    constexpr int MT = WM / 16;
    extern __shared__ __align__(128) bf16 sm[];
    __shared__ float s_bias[BN];

    const int tid = threadIdx.x, w = tid >> 5, lane = tid & 31;
    const int wx = w % NWX, wy = w / NWX;
    const int m0 = blockIdx.y * BM, n0 = blockIdx.x * BN;
    const uint32_t smb = smem_u32(sm);

    for (int i = tid; i < BN; i += NT) s_bias[i] = bias[n0 + i];

    const bf16* Ah = gAhi + (size_t)m0 * KTOT;
    const bf16* Al = gAlo + (size_t)m0 * KTOT;
    const bf16* Bh = gBhi + (size_t)n0 * BSTR;
    const bf16* Bl = gBlo + (size_t)n0 * BSTR;

    float acc[MT][4][4];
#pragma unroll
    for (int i = 0; i < MT; i++)
#pragma unroll
        for (int j = 0; j < 4; j++)
#pragma unroll
            for (int k = 0; k < 4; k++) acc[i][j][k] = 0.0f;

    load_stage<BM, BN, NT, BSTR>(0, smb, tid, Ah, Al, Bh, Bl);

    for (int s = 0; s < NCH; s++) {
        if (s + 1 < NCH) {
            load_stage<BM, BN, NT, BSTR>(s + 1, smb, tid, Ah, Al, Bh, Bl);
            asm volatile("cp.async.wait_group 1;");
        } else {
            asm volatile("cp.async.wait_group 0;");
        }
        __syncthreads();

        constexpr uint32_t STAGE_B = (BM + BN) * 2u * 144u;
        uint32_t st   = smb + (uint32_t)(s & 1) * STAGE_B;
        uint32_t stBh = st + 2u * BM * 144u;
#pragma unroll
        for (int ks = 0; ks < 4; ks++) {
            const int kk = ks * 16;
            uint32_t ah[MT][4], alr[MT][4];
#pragma unroll
            for (int mt = 0; mt < MT; mt++) {
                uint32_t addr = st + (uint32_t)((wy * WM + mt * 16 + (lane & 15)) * 144
                               + (kk + ((lane >> 4) << 3)) * 2);
                LDSM4(ah[mt], addr);
                LDSM4(alr[mt], addr + BM * 144u);
            }
            uint32_t bh[8], bl[8];
#pragma unroll
            for (int nb = 0; nb < 2; nb++) {
                int gg = lane >> 3;
                uint32_t addr = stBh + (uint32_t)((wx * 32 + nb * 16 + ((gg >> 1) << 3)
                               + (lane & 7)) * 144 + (kk + ((gg & 1) << 3)) * 2);
                LDSM4(bh + nb * 4, addr);
                LDSM4(bl + nb * 4, addr + BN * 144u);
            }
#pragma unroll
            for (int mt = 0; mt < MT; mt++)
#pragma unroll
                for (int nt = 0; nt < 4; nt++) {
                    const uint32_t* ph = bh + (nt >> 1) * 4 + (nt & 1) * 2;
                    const uint32_t* pl = bl + (nt >> 1) * 4 + (nt & 1) * 2;
                    mma16816(acc[mt][nt], ah[mt],  ph);
                    mma16816(acc[mt][nt], ah[mt],  pl);
                    mma16816(acc[mt][nt], alr[mt], ph);
                }
        }
        __syncthreads();
    }

    const int a_ = lane & 3, rl = lane >> 2;
    if constexpr (GATES) {
#pragma unroll
        for (int mt = 0; mt < MT; mt++)
#pragma unroll
            for (int p = 0; p < 2; p++) {
                const int colb = wx * 32 + p * 16;
                const float bi = s_bias[colb + 2 * a_];
                const float bf = s_bias[colb + 2 * a_ + 1];
                const float bg = s_bias[colb + 8 + 2 * a_];
                const float bo = s_bias[colb + 8 + 2 * a_ + 1];
                const int j = ((n0 + colb) >> 2) + a_;
#pragma unroll
                for (int rh = 0; rh < 2; rh++) {
                    float iv = acc[mt][2 * p][2 * rh]     + bi;
                    float fv = acc[mt][2 * p][2 * rh + 1] + bf;
                    float gv = acc[mt][2 * p + 1][2 * rh]     + bg;
                    float ov = acc[mt][2 * p + 1][2 * rh + 1] + bo;
                    int b = m0 + wy * WM + mt * 16 + rh * 8 + rl;
                    size_t cidx = (size_t)b * H_ + j;
                    float c = sigmf(fv) * g_c[cidx] + sigmf(iv) * tanhf(gv);
                    float h = sigmf(ov) * tanhf(c);
                    g_c[cidx] = c;
                    g_hmax[cidx] = fmaxf(g_hmax[cidx], h);
                    bf16 hh = __float2bfloat16(h);
                    size_t widx = (size_t)b * KTOT + HOFF + j;
                    wAhi[widx] = hh;
                    wAlo[widx] = __float2bfloat16(h - __bfloat162float(hh));
                }
            }
    } else {
#pragma unroll
        for (int mt = 0; mt < MT; mt++)
#pragma unroll
            for (int nt = 0; nt < 4; nt++) {
                const int lc = wx * 32 + nt * 8 + 2 * a_;
#pragma unroll
                for (int rh = 0; rh < 2; rh++) {
                    int row = m0 + wy * WM + mt * 16 + rh * 8 + rl;
                    float2 v;
                    v.x = acc[mt][nt][2 * rh]     + s_bias[lc];
                    v.y = acc[mt][nt][2 * rh + 1] + s_bias[lc + 1];
                    *(float2*)&g_logits[(size_t)row * NATT + n0 + lc] = v;
                }
            }
    }
}

// ---------------- fused softmax + attention pooling (writes v as bf16 hi/lo) ----------------
__global__ void k_attn(const float* __restrict__ X, bf16* __restrict__ wHi,
                       bf16* __restrict__ wLo) {
    __shared__ float alp[NATT];
    __shared__ float xs[16 * DIN];
    __shared__ float red[16];
    const int b = blockIdx.x;
    const int tid = threadIdx.x;
    for (int i = tid; i < NATT; i += 416) alp[i] = g_logits[b * NATT + i];
    __syncthreads();

    const int wid = tid >> 5, lane = tid & 31;
    float xv = (tid < NATT) ? alp[tid] : -FLT_MAX;
    float m = xv;
#pragma unroll
    for (int off = 16; off; off >>= 1) m = fmaxf(m, __shfl_xor_sync(0xffffffffu, m, off));
    if (lane == 0) red[wid] = m;
    __syncthreads();
    if (tid < NATT) {
        int k4 = (tid >> 7) << 2;
        float rm = fmaxf(fmaxf(red[k4], red[k4 + 1]), fmaxf(red[k4 + 2], red[k4 + 3]));
        xv = expf(xv - rm);
    } else xv = 0.0f;
    __syncthreads();
    float s = xv;
#pragma unroll
    for (int off = 16; off; off >>= 1) s += __shfl_xor_sync(0xffffffffu, s, off);
    if (lane == 0) red[wid] = s;
    __syncthreads();
    if (tid < NATT) {
        int k4 = (tid >> 7) << 2;
        float rs = red[k4] + red[k4 + 1] + red[k4 + 2] + red[k4 + 3];
        alp[tid] = xv / rs;
    }
    __syncthreads();

    float acc = 0.0f;
    const int k = tid / DIN, d = tid - k * DIN;
    const float* Xb = X + (size_t)b * (L_ * DIN);
    for (int lc = 0; lc < L_; lc += 16) {
        for (int i = tid; i < 16 * DIN; i += 416) xs[i] = Xb[lc * DIN + i];
        __syncthreads();
        if (tid < 390) {
#pragma unroll
            for (int l = 0; l < 16; l++) acc += alp[k * L_ + lc + l] * xs[l * DIN + d];
        }
        __syncthreads();
    }
    if (tid < 390) {
        bf16 hi = __float2bfloat16(acc);
        wHi[(size_t)b * KTOT + tid] = hi;
        wLo[(size_t)b * KTOT + tid] = __float2bfloat16(acc - __bfloat162float(hi));
    }
}

// ---------------- fused tail ----------------
__global__ void k_tail(const float* __restrict__ Fe, const float* __restrict__ W_d1,
                       const float* __restrict__ b_d1, const float* __restrict__ W_r,
                       const float* __restrict__ b_r, const float* __restrict__ W_a,
                       const float* __restrict__ W_d2, const float* __restrict__ b_d2,
                       float* __restrict__ out) {
    __shared__ float hs[H_];
    __shared__ float yb[FEAT_];
    __shared__ float r1[PROJ_], r2[PROJ_], sb[PROJ_];
    __shared__ float aw[2];
    const int b = blockIdx.x, tid = threadIdx.x;   // 64 threads
    for (int i = tid; i < H_; i += 64) hs[i] = g_hmax[(size_t)b * H_ + i];
    __syncthreads();
    if (tid < FEAT_) {
        float a = b_d1[tid];
        const float* w = W_d1 + tid * H_;
        for (int k2 = 0; k2 < H_; k2++) a += hs[k2] * w[k2];
        yb[tid] = fmaxf(a, 0.0f);
    }
    __syncthreads();
    if (tid < PROJ_) {
        float a = b_r[tid], a2 = b_r[tid];
        const float* w = W_r + tid * FEAT_;
        const float* fe = Fe + b * FEAT_;
        for (int q = 0; q < FEAT_; q++) { a += yb[q] * w[q]; a2 += fe[q] * w[q]; }
        r1[tid] = a  > 0.0f ? a  : 0.01f * a;
        r2[tid] = a2 > 0.0f ? a2 : 0.01f * a2;
    }
    __syncthreads();
    if (tid == 0) {
        float s1 = 0.0f, s2 = 0.0f;
        for (int p = 0; p < PROJ_; p++) { s1 += tanhf(r1[p]) * W_a[p]; s2 += tanhf(r2[p]) * W_a[p]; }
        float mx = fmaxf(s1, s2);
        float e1 = expf(s1 - mx), e2 = expf(s2 - mx);
        float inv = 1.0f / (e1 + e2);
        aw[0] = e1 * inv; aw[1] = e2 * inv;
    }
    __syncthreads();
    if (tid < PROJ_) sb[tid] = fmaxf(aw[0] * r1[tid] + aw[1] * r2[tid], 0.0f);
    __syncthreads();
    if (tid < 2) {
        float a = b_d2[tid];
        const float* w = W_d2 + tid * PROJ_;
        for (int p = 0; p < PROJ_; p++) a += sb[p] * w[p];
        out[b * 2 + tid] = a;
    }
}

// ---------------- launch ----------------
extern "C" void kernel_launch(void* const* d_in, const int* in_sizes, int n_in,
                              void* d_out, int out_size) {
    const float* X     = (const float*)d_in[0];
    const float* Fe    = (const float*)d_in[1];
    const float* W_att = (const float*)d_in[2];
    const float* b_att = (const float*)d_in[3];
    const float* W_ih  = (const float*)d_in[4];
    const float* W_hh  = (const float*)d_in[5];
    const float* b_ih  = (const float*)d_in[6];
    const float* b_hh  = (const float*)d_in[7];
    const float* W_d1  = (const float*)d_in[8];
    const float* b_d1  = (const float*)d_in[9];
    const float* W_r   = (const float*)d_in[10];
    const float* b_r   = (const float*)d_in[11];
    const float* W_a   = (const float*)d_in[12];
    const float* W_d2  = (const float*)d_in[13];
    const float* b_d2  = (const float*)d_in[14];
    float* out = (float*)d_out;

    bf16 *Ah0, *Al0, *Ah1, *Al1, *Whi, *Wlo, *Lhi, *Llo;
    float *bsum;
    cudaGetSymbolAddress((void**)&Ah0, g_Ahi0);
    cudaGetSymbolAddress((void**)&Al0, g_Alo0);
    cudaGetSymbolAddress((void**)&Ah1, g_Ahi1);
    cudaGetSymbolAddress((void**)&Al1, g_Alo1);
    cudaGetSymbolAddress((void**)&Whi, g_Whi);
    cudaGetSymbolAddress((void**)&Wlo, g_Wlo);
    cudaGetSymbolAddress((void**)&Lhi, g_Lhi);
    cudaGetSymbolAddress((void**)&Llo, g_Llo);
    cudaGetSymbolAddress((void**)&bsum, g_bsum);

    constexpr int DSMEM_G = 2 * (128 + 128) * 2 * 144;   // 147456 B
    constexpr int DSMEM_L = 2 * (64 + 64) * 2 * 144;     //  73728 B
    cudaFuncSetAttribute((const void*)k_mma<128, 128, 32, true,  KTOT, NCH_G>,
                         cudaFuncAttributeMaxDynamicSharedMemorySize, DSMEM_G);
    cudaFuncSetAttribute((const void*)k_mma<64, 64, 16, false, H_,  NCH_L>,
                         cudaFuncAttributeMaxDynamicSharedMemorySize, DSMEM_L);

    k_init<<<2048, 256>>>(W_att, W_ih, W_hh, b_ih, b_hh);

    for (int t = 0; t < L_; t++) {
        bf16* rdHi = (t & 1) ? Ah1 : Ah0;
        bf16* rdLo = (t & 1) ? Al1 : Al0;
        bf16* wrHi = (t & 1) ? Ah0 : Ah1;
        bf16* wrLo = (t & 1) ? Al0 : Al1;
        // logits[1024,384] = h @ Wl + b_att   (8 warps now)
        k_mma<64, 64, 16, false, H_, NCH_L><<<dim3(NATT / 64, B_ / 64), 256, DSMEM_L>>>(
            rdHi + HOFF, rdLo + HOFF, nullptr, nullptr, Lhi, Llo, b_att);
        // softmax + attention pooling -> v into rd buffer
        k_attn<<<B_, 416>>>(X, rdHi, rdLo);
        // gates = [v|h] @ Wcat + bsum, fused LSTM cell -> h into wr buffer (16 warps now)
        k_mma<128, 128, 32, true, KTOT, NCH_G><<<dim3(NG / 128, B_ / 128), 512, DSMEM_G>>>(
            rdHi, rdLo, wrHi, wrLo, Whi, Wlo, bsum);
    }

    k_tail<<<B_, 64>>>(Fe, W_d1, b_d1, W_r, b_r, W_a, W_d2, b_d2, out);
}

// round 6
// speedup vs baseline: 2.2677x; 1.1509x over previous
#include <cuda_runtime.h>
#include <cuda_bf16.h>
#include <math.h>
#include <float.h>
#include <stdint.h>

#define B_    1024
#define L_    128
#define DIN   130
#define H_    768
#define FEAT_ 49
#define PROJ_ 40
#define NG    3072          // 4*H
#define NATT  384           // 3*L
#define KTOT  1184          // padded K: [0,390)=v, [400,1168)=h, [1168,1184)=0
#define HOFF  400
#define NCH_G 37            // KTOT/32
#define NCH_L 24            // 768/32

typedef __nv_bfloat16 bf16;

// ---------------- device scratch ----------------
__device__ bf16 g_Ahi0[B_*KTOT], g_Alo0[B_*KTOT];   // ping-pong A (hi/lo split)
__device__ bf16 g_Ahi1[B_*KTOT], g_Alo1[B_*KTOT];
__device__ bf16 g_Whi[NG*KTOT],  g_Wlo[NG*KTOT];    // gates W^T [n_perm][k]
__device__ bf16 g_Lhi[NATT*H_],  g_Llo[NATT*H_];    // logits W^T [n][k]
__device__ float g_bsum[NG];                        // b_ih+b_hh, permuted
__device__ float g_c[B_*H_], g_hmax[B_*H_];         // [b][j]
__device__ float g_logits[B_*NATT];

// ---------------- helpers ----------------
__device__ __forceinline__ uint32_t smem_u32(const void* p) {
    return (uint32_t)__cvta_generic_to_shared(p);
}
__device__ __forceinline__ void cpa16(uint32_t dst, const void* src) {
    asm volatile("cp.async.cg.shared.global [%0], [%1], 16;"
                 :: "r"(dst), "l"(__cvta_generic_to_global(src)));
}
#define CPA_COMMIT() asm volatile("cp.async.commit_group;")

#define LDSM4(r, a) \
    asm volatile("ldmatrix.sync.aligned.m8n8.x4.shared.b16 {%0,%1,%2,%3}, [%4];" \
        : "=r"((r)[0]), "=r"((r)[1]), "=r"((r)[2]), "=r"((r)[3]) : "r"(a))

__device__ __forceinline__ void mma16816(float* d, const uint32_t* a, const uint32_t* b) {
    asm volatile("mma.sync.aligned.m16n8k16.row.col.f32.bf16.bf16.f32 "
        "{%0,%1,%2,%3}, {%4,%5,%6,%7}, {%8,%9}, {%0,%1,%2,%3};"
        : "+f"(d[0]), "+f"(d[1]), "+f"(d[2]), "+f"(d[3])
        : "r"(a[0]), "r"(a[1]), "r"(a[2]), "r"(a[3]), "r"(b[0]), "r"(b[1]));
}

__device__ __forceinline__ float sigmf(float x) { return 1.0f / (1.0f + __expf(-x)); }

// ---------------- init: bf16 hi/lo weight builds, gate-permuted columns ----------------
// permuted col n = 16q + 8h + 2a + e  <->  gate (2h+e) of hidden j = 4q + a
__global__ void k_init(const float* __restrict__ W_att, const float* __restrict__ W_ih,
                       const float* __restrict__ W_hh, const float* __restrict__ b_ih,
                       const float* __restrict__ b_hh) {
    long g = (long)blockIdx.x * blockDim.x + threadIdx.x;
    long stride = (long)gridDim.x * blockDim.x;
    for (long i = g; i < (long)NG * KTOT; i += stride) {
        int n = (int)(i / KTOT), k = (int)(i % KTOT);
        int q = n >> 4, r = n & 15;
        int gate = ((r >> 3) << 1) | (r & 1);
        int j = (q << 2) + ((r & 7) >> 1);
        int srow = gate * H_ + j;
        float w = 0.0f;
        if (k < 390)                         w = W_ih[(size_t)srow * 390 + k];
        else if (k >= HOFF && k < HOFF + H_) w = W_hh[(size_t)srow * H_ + (k - HOFF)];
        bf16 hi = __float2bfloat16(w);
        g_Whi[i] = hi;
        g_Wlo[i] = __float2bfloat16(w - __bfloat162float(hi));
    }
    for (long i = g; i < (long)NATT * H_; i += stride) {
        int n = (int)(i / H_), k = (int)(i % H_);
        int ks = n >> 7, l = n & 127;
        float w = W_att[(size_t)ks * (H_ * L_) + (size_t)k * L_ + l];
        bf16 hi = __float2bfloat16(w);
        g_Lhi[i] = hi;
        g_Llo[i] = __float2bfloat16(w - __bfloat162float(hi));
    }
    for (long i = g; i < NG; i += stride) {
        int n = (int)i;
        int q = n >> 4, r = n & 15;
        int gate = ((r >> 3) << 1) | (r & 1);
        int j = (q << 2) + ((r & 7) >> 1);
        g_bsum[i] = b_ih[gate * H_ + j] + b_hh[gate * H_ + j];
    }
    bf16 z = __float2bfloat16(0.0f);
    for (long i = g; i < (long)B_ * KTOT; i += stride) {
        g_Ahi0[i] = z; g_Alo0[i] = z; g_Ahi1[i] = z; g_Alo1[i] = z;
    }
    for (long i = g; i < (long)B_ * H_; i += stride) { g_c[i] = 0.0f; g_hmax[i] = -FLT_MAX; }
}

// ---------------- stage loader: global -> smem (Ahi,Alo,Bhi,Blo) ----------------
// row stride = BK*2+16 bytes (pad kills ldmatrix bank conflicts)
template <int BM, int BN, int BK, int NT, int BSTR>
__device__ __forceinline__ void load_stage(int s, uint32_t smbase, int tid,
                                           const bf16* __restrict__ Ah,
                                           const bf16* __restrict__ Al,
                                           const bf16* __restrict__ Bh,
                                           const bf16* __restrict__ Bl) {
    constexpr int RS = BK * 2 + 16;
    constexpr int SEG = BK / 8;                 // 16B segments per row
    constexpr uint32_t STAGE_B = (BM + BN) * 2u * (uint32_t)RS;
    uint32_t st   = smbase + (uint32_t)(s & 1) * STAGE_B;
    uint32_t stAl = st + BM * (uint32_t)RS;
    uint32_t stBh = st + 2u * BM * (uint32_t)RS;
    uint32_t stBl = stBh + BN * (uint32_t)RS;
    const int k0 = s * BK;
#pragma unroll
    for (int r = 0; r < (BM * SEG) / NT; r++) {
        int i = tid + r * NT, row = i / SEG, seg = i % SEG;
        uint32_t off = row * RS + seg * 16;
        size_t go = (size_t)row * KTOT + k0 + seg * 8;
        cpa16(st + off,   Ah + go);
        cpa16(stAl + off, Al + go);
    }
#pragma unroll
    for (int r = 0; r < (BN * SEG) / NT; r++) {
        int i = tid + r * NT, row = i / SEG, seg = i % SEG;
        uint32_t off = row * RS + seg * 16;
        size_t go = (size_t)row * BSTR + k0 + seg * 8;
        cpa16(stBh + off, Bh + go);
        cpa16(stBl + off, Bl + go);
    }
    CPA_COMMIT();
}

// ---------------- mma.sync GEMM, hi/lo 3-product, fused epilogue ----------------
// GATES=true : epilogue = LSTM cell, writes h (hi/lo) into write A buffer
// GATES=false: epilogue = logits + bias
template <int BM, int BN, int BK, int WM, bool GATES, int BSTR, int NCH>
__global__ void __launch_bounds__((BM / WM) * (BN / 32) * 32, 2)
k_mma(const bf16* __restrict__ gAhi, const bf16* __restrict__ gAlo,
      bf16* __restrict__ wAhi, bf16* __restrict__ wAlo,
      const bf16* __restrict__ gBhi, const bf16* __restrict__ gBlo,
      const float* __restrict__ bias) {
    constexpr int NWX = BN / 32, NWY = BM / WM, NT = NWX * NWY * 32;
    constexpr int MT = WM / 16;
    constexpr int RS = BK * 2 + 16;
    extern __shared__ __align__(128) bf16 sm[];
    __shared__ float s_bias[BN];

    const int tid = threadIdx.x, w = tid >> 5, lane = tid & 31;
    const int wx = w % NWX, wy = w / NWX;
    const int m0 = blockIdx.y * BM, n0 = blockIdx.x * BN;
    const uint32_t smb = smem_u32(sm);

    for (int i = tid; i < BN; i += NT) s_bias[i] = bias[n0 + i];

    const bf16* Ah = gAhi + (size_t)m0 * KTOT;
    const bf16* Al = gAlo + (size_t)m0 * KTOT;
    const bf16* Bh = gBhi + (size_t)n0 * BSTR;
    const bf16* Bl = gBlo + (size_t)n0 * BSTR;

    float acc[MT][4][4];
#pragma unroll
    for (int i = 0; i < MT; i++)
#pragma unroll
        for (int j = 0; j < 4; j++)
#pragma unroll
            for (int k = 0; k < 4; k++) acc[i][j][k] = 0.0f;

    load_stage<BM, BN, BK, NT, BSTR>(0, smb, tid, Ah, Al, Bh, Bl);

    for (int s = 0; s < NCH; s++) {
        if (s + 1 < NCH) {
            load_stage<BM, BN, BK, NT, BSTR>(s + 1, smb, tid, Ah, Al, Bh, Bl);
            asm volatile("cp.async.wait_group 1;");
        } else {
            asm volatile("cp.async.wait_group 0;");
        }
        __syncthreads();

        constexpr uint32_t STAGE_B = (BM + BN) * 2u * (uint32_t)RS;
        uint32_t st   = smb + (uint32_t)(s & 1) * STAGE_B;
        uint32_t stBh = st + 2u * BM * (uint32_t)RS;
#pragma unroll
        for (int ks = 0; ks < BK / 16; ks++) {
            const int kk = ks * 16;
            uint32_t ah[MT][4], alr[MT][4];
#pragma unroll
            for (int mt = 0; mt < MT; mt++) {
                uint32_t addr = st + (uint32_t)((wy * WM + mt * 16 + (lane & 15)) * RS
                               + (kk + ((lane >> 4) << 3)) * 2);
                LDSM4(ah[mt], addr);
                LDSM4(alr[mt], addr + BM * (uint32_t)RS);
            }
            uint32_t bh[8], bl[8];
#pragma unroll
            for (int nb = 0; nb < 2; nb++) {
                int gg = lane >> 3;
                uint32_t addr = stBh + (uint32_t)((wx * 32 + nb * 16 + ((gg >> 1) << 3)
                               + (lane & 7)) * RS + (kk + ((gg & 1) << 3)) * 2);
                LDSM4(bh + nb * 4, addr);
                LDSM4(bl + nb * 4, addr + BN * (uint32_t)RS);
            }
#pragma unroll
            for (int mt = 0; mt < MT; mt++)
#pragma unroll
                for (int nt = 0; nt < 4; nt++) {
                    const uint32_t* ph = bh + (nt >> 1) * 4 + (nt & 1) * 2;
                    const uint32_t* pl = bl + (nt >> 1) * 4 + (nt & 1) * 2;
                    mma16816(acc[mt][nt], ah[mt],  ph);
                    mma16816(acc[mt][nt], ah[mt],  pl);
                    mma16816(acc[mt][nt], alr[mt], ph);
                }
        }
        __syncthreads();
    }

    const int a_ = lane & 3, rl = lane >> 2;
    if constexpr (GATES) {
#pragma unroll
        for (int mt = 0; mt < MT; mt++)
#pragma unroll
            for (int p = 0; p < 2; p++) {
                const int colb = wx * 32 + p * 16;
                const float bi = s_bias[colb + 2 * a_];
                const float bf = s_bias[colb + 2 * a_ + 1];
                const float bg = s_bias[colb + 8 + 2 * a_];
                const float bo = s_bias[colb + 8 + 2 * a_ + 1];
                const int j = ((n0 + colb) >> 2) + a_;
#pragma unroll
                for (int rh = 0; rh < 2; rh++) {
                    float iv = acc[mt][2 * p][2 * rh]     + bi;
                    float fv = acc[mt][2 * p][2 * rh + 1] + bf;
                    float gv = acc[mt][2 * p + 1][2 * rh]     + bg;
                    float ov = acc[mt][2 * p + 1][2 * rh + 1] + bo;
                    int b = m0 + wy * WM + mt * 16 + rh * 8 + rl;
                    size_t cidx = (size_t)b * H_ + j;
                    float c = sigmf(fv) * g_c[cidx] + sigmf(iv) * tanhf(gv);
                    float h = sigmf(ov) * tanhf(c);
                    g_c[cidx] = c;
                    g_hmax[cidx] = fmaxf(g_hmax[cidx], h);
                    bf16 hh = __float2bfloat16(h);
                    size_t widx = (size_t)b * KTOT + HOFF + j;
                    wAhi[widx] = hh;
                    wAlo[widx] = __float2bfloat16(h - __bfloat162float(hh));
                }
            }
    } else {
#pragma unroll
        for (int mt = 0; mt < MT; mt++)
#pragma unroll
            for (int nt = 0; nt < 4; nt++) {
                const int lc = wx * 32 + nt * 8 + 2 * a_;
#pragma unroll
                for (int rh = 0; rh < 2; rh++) {
                    int row = m0 + wy * WM + mt * 16 + rh * 8 + rl;
                    float2 v;
                    v.x = acc[mt][nt][2 * rh]     + s_bias[lc];
                    v.y = acc[mt][nt][2 * rh + 1] + s_bias[lc + 1];
                    *(float2*)&g_logits[(size_t)row * NATT + n0 + lc] = v;
                }
            }
    }
}

// ---------------- fused softmax + attention pooling (writes v as bf16 hi/lo) ----------------
__global__ void k_attn(const float* __restrict__ X, bf16* __restrict__ wHi,
                       bf16* __restrict__ wLo) {
    __shared__ float alp[NATT];
    __shared__ float xs[16 * DIN];
    __shared__ float red[16];
    const int b = blockIdx.x;
    const int tid = threadIdx.x;
    for (int i = tid; i < NATT; i += 416) alp[i] = g_logits[b * NATT + i];
    __syncthreads();

    const int wid = tid >> 5, lane = tid & 31;
    float xv = (tid < NATT) ? alp[tid] : -FLT_MAX;
    float m = xv;
#pragma unroll
    for (int off = 16; off; off >>= 1) m = fmaxf(m, __shfl_xor_sync(0xffffffffu, m, off));
    if (lane == 0) red[wid] = m;
    __syncthreads();
    if (tid < NATT) {
        int k4 = (tid >> 7) << 2;
        float rm = fmaxf(fmaxf(red[k4], red[k4 + 1]), fmaxf(red[k4 + 2], red[k4 + 3]));
        xv = expf(xv - rm);
    } else xv = 0.0f;
    __syncthreads();
    float s = xv;
#pragma unroll
    for (int off = 16; off; off >>= 1) s += __shfl_xor_sync(0xffffffffu, s, off);
    if (lane == 0) red[wid] = s;
    __syncthreads();
    if (tid < NATT) {
        int k4 = (tid >> 7) << 2;
        float rs = red[k4] + red[k4 + 1] + red[k4 + 2] + red[k4 + 3];
        alp[tid] = xv / rs;
    }
    __syncthreads();

    float acc = 0.0f;
    const int k = tid / DIN, d = tid - k * DIN;
    const float* Xb = X + (size_t)b * (L_ * DIN);
    for (int lc = 0; lc < L_; lc += 16) {
        for (int i = tid; i < 16 * DIN; i += 416) xs[i] = Xb[lc * DIN + i];
        __syncthreads();
        if (tid < 390) {
#pragma unroll
            for (int l = 0; l < 16; l++) acc += alp[k * L_ + lc + l] * xs[l * DIN + d];
        }
        __syncthreads();
    }
    if (tid < 390) {
        bf16 hi = __float2bfloat16(acc);
        wHi[(size_t)b * KTOT + tid] = hi;
        wLo[(size_t)b * KTOT + tid] = __float2bfloat16(acc - __bfloat162float(hi));
    }
}

// ---------------- fused tail ----------------
__global__ void k_tail(const float* __restrict__ Fe, const float* __restrict__ W_d1,
                       const float* __restrict__ b_d1, const float* __restrict__ W_r,
                       const float* __restrict__ b_r, const float* __restrict__ W_a,
                       const float* __restrict__ W_d2, const float* __restrict__ b_d2,
                       float* __restrict__ out) {
    __shared__ float hs[H_];
    __shared__ float yb[FEAT_];
    __shared__ float r1[PROJ_], r2[PROJ_], sb[PROJ_];
    __shared__ float aw[2];
    const int b = blockIdx.x, tid = threadIdx.x;   // 64 threads
    for (int i = tid; i < H_; i += 64) hs[i] = g_hmax[(size_t)b * H_ + i];
    __syncthreads();
    if (tid < FEAT_) {
        float a = b_d1[tid];
        const float* w = W_d1 + tid * H_;
        for (int k2 = 0; k2 < H_; k2++) a += hs[k2] * w[k2];
        yb[tid] = fmaxf(a, 0.0f);
    }
    __syncthreads();
    if (tid < PROJ_) {
        float a = b_r[tid], a2 = b_r[tid];
        const float* w = W_r + tid * FEAT_;
        const float* fe = Fe + b * FEAT_;
        for (int q = 0; q < FEAT_; q++) { a += yb[q] * w[q]; a2 += fe[q] * w[q]; }
        r1[tid] = a  > 0.0f ? a  : 0.01f * a;
        r2[tid] = a2 > 0.0f ? a2 : 0.01f * a2;
    }
    __syncthreads();
    if (tid == 0) {
        float s1 = 0.0f, s2 = 0.0f;
        for (int p = 0; p < PROJ_; p++) { s1 += tanhf(r1[p]) * W_a[p]; s2 += tanhf(r2[p]) * W_a[p]; }
        float mx = fmaxf(s1, s2);
        float e1 = expf(s1 - mx), e2 = expf(s2 - mx);
        float inv = 1.0f / (e1 + e2);
        aw[0] = e1 * inv; aw[1] = e2 * inv;
    }
    __syncthreads();
    if (tid < PROJ_) sb[tid] = fmaxf(aw[0] * r1[tid] + aw[1] * r2[tid], 0.0f);
    __syncthreads();
    if (tid < 2) {
        float a = b_d2[tid];
        const float* w = W_d2 + tid * PROJ_;
        for (int p = 0; p < PROJ_; p++) a += sb[p] * w[p];
        out[b * 2 + tid] = a;
    }
}

// ---------------- launch ----------------
extern "C" void kernel_launch(void* const* d_in, const int* in_sizes, int n_in,
                              void* d_out, int out_size) {
    const float* X     = (const float*)d_in[0];
    const float* Fe    = (const float*)d_in[1];
    const float* W_att = (const float*)d_in[2];
    const float* b_att = (const float*)d_in[3];
    const float* W_ih  = (const float*)d_in[4];
    const float* W_hh  = (const float*)d_in[5];
    const float* b_ih  = (const float*)d_in[6];
    const float* b_hh  = (const float*)d_in[7];
    const float* W_d1  = (const float*)d_in[8];
    const float* b_d1  = (const float*)d_in[9];
    const float* W_r   = (const float*)d_in[10];
    const float* b_r   = (const float*)d_in[11];
    const float* W_a   = (const float*)d_in[12];
    const float* W_d2  = (const float*)d_in[13];
    const float* b_d2  = (const float*)d_in[14];
    float* out = (float*)d_out;

    bf16 *Ah0, *Al0, *Ah1, *Al1, *Whi, *Wlo, *Lhi, *Llo;
    float *bsum;
    cudaGetSymbolAddress((void**)&Ah0, g_Ahi0);
    cudaGetSymbolAddress((void**)&Al0, g_Alo0);
    cudaGetSymbolAddress((void**)&Ah1, g_Ahi1);
    cudaGetSymbolAddress((void**)&Al1, g_Alo1);
    cudaGetSymbolAddress((void**)&Whi, g_Whi);
    cudaGetSymbolAddress((void**)&Wlo, g_Wlo);
    cudaGetSymbolAddress((void**)&Lhi, g_Lhi);
    cudaGetSymbolAddress((void**)&Llo, g_Llo);
    cudaGetSymbolAddress((void**)&bsum, g_bsum);

    // gates: 128x64 tile, BK=32, 2-stage: (128+64)*2*80*2 = 61440 B
    constexpr int DSMEM_G = 2 * (128 + 64) * 2 * 80;
    // logits: 64x64 tile, BK=32, 2-stage: (64+64)*2*80*2 = 40960 B
    constexpr int DSMEM_L = 2 * (64 + 64) * 2 * 80;
    cudaFuncSetAttribute((const void*)k_mma<128, 64, 32, 32, true,  KTOT, NCH_G>,
                         cudaFuncAttributeMaxDynamicSharedMemorySize, DSMEM_G);
    cudaFuncSetAttribute((const void*)k_mma<64, 64, 32, 16, false, H_,  NCH_L>,
                         cudaFuncAttributeMaxDynamicSharedMemorySize, DSMEM_L);

    k_init<<<2048, 256>>>(W_att, W_ih, W_hh, b_ih, b_hh);

    for (int t = 0; t < L_; t++) {
        bf16* rdHi = (t & 1) ? Ah1 : Ah0;
        bf16* rdLo = (t & 1) ? Al1 : Al0;
        bf16* wrHi = (t & 1) ? Ah0 : Ah1;
        bf16* wrLo = (t & 1) ? Al0 : Al1;
        // logits[1024,384] = h @ Wl + b_att
        k_mma<64, 64, 32, 16, false, H_, NCH_L><<<dim3(NATT / 64, B_ / 64), 256, DSMEM_L>>>(
            rdHi + HOFF, rdLo + HOFF, nullptr, nullptr, Lhi, Llo, b_att);
        // softmax + attention pooling -> v into rd buffer
        k_attn<<<B_, 416>>>(X, rdHi, rdLo);
        // gates = [v|h] @ Wcat + bsum, fused LSTM cell -> h into wr buffer
        k_mma<128, 64, 32, 32, true, KTOT, NCH_G><<<dim3(NG / 64, B_ / 128), 256, DSMEM_G>>>(
            rdHi, rdLo, wrHi, wrLo, Whi, Wlo, bsum);
    }

    k_tail<<<B_, 64>>>(Fe, W_d1, b_d1, W_r, b_r, W_a, W_d2, b_d2, out);
}

// round 7
// speedup vs baseline: 2.4487x; 1.0798x over previous
#include <cuda_runtime.h>
#include <cuda_bf16.h>
#include <math.h>
#include <float.h>
#include <stdint.h>

#define B_    1024
#define L_    128
#define DIN   130
#define H_    768
#define FEAT_ 49
#define PROJ_ 40
#define NG    3072          // 4*H
#define NATT  384           // 3*L
#define NCHK  37            // total K chunks of 32: v chunks 0..12, h chunks 13..36
#define HOFF  416           // h starts at k=416 (chunk 13)
#define KTOT  1184

typedef __nv_bfloat16 bf16;

// ---------------- device scratch (chunked, swizzled layouts) ----------------
// A: [chunk][1024 rows][32 k]  (bf16), swizzled within each row's 64B
__device__ bf16 g_Ahi0[NCHK*B_*32], g_Alo0[NCHK*B_*32];
__device__ bf16 g_Ahi1[NCHK*B_*32], g_Alo1[NCHK*B_*32];
__device__ bf16 g_Whi[NCHK*NG*32],  g_Wlo[NCHK*NG*32];   // gates W^T chunked [c][n_perm][32]
__device__ bf16 g_Lhi[24*NATT*32],  g_Llo[24*NATT*32];   // logits W^T chunked [c][n][32]
__device__ float g_bsum[NG];
__device__ float g_c[B_*H_], g_hmax[B_*H_];
__device__ float g_logits[B_*NATT];

// ---------------- helpers ----------------
__device__ __forceinline__ uint32_t smem_u32(const void* p) {
    return (uint32_t)__cvta_generic_to_shared(p);
}
// element offset inside one chunk block for (row, kk): 64B rows, XOR seg swizzle
__device__ __forceinline__ int swz(int row, int kk) {
    int seg = ((kk >> 3) ^ (row + (row >> 2))) & 3;
    return row * 32 + seg * 8 + (kk & 7);
}
__device__ __forceinline__ void bulk_cp(uint32_t dst, const void* src, uint32_t bytes,
                                        uint32_t mbar) {
    asm volatile("cp.async.bulk.shared::cluster.global.mbarrier::complete_tx::bytes "
                 "[%0], [%1], %2, [%3];"
                 :: "r"(dst), "l"(__cvta_generic_to_global(src)), "r"(bytes), "r"(mbar)
                 : "memory");
}
__device__ __forceinline__ void mbar_init(uint32_t a, uint32_t cnt) {
    asm volatile("mbarrier.init.shared.b64 [%0], %1;" :: "r"(a), "r"(cnt) : "memory");
}
__device__ __forceinline__ void mbar_expect(uint32_t a, uint32_t tx) {
    asm volatile("mbarrier.arrive.expect_tx.shared.b64 _, [%0], %1;"
                 :: "r"(a), "r"(tx) : "memory");
}
__device__ __forceinline__ void mbar_wait(uint32_t a, uint32_t ph) {
    asm volatile(
        "{\n\t.reg .pred P;\n"
        "WL%=:\n\t"
        "mbarrier.try_wait.parity.acquire.cta.shared::cta.b64 P, [%0], %1, 0x989680;\n\t"
        "@P bra WD%=;\n\t"
        "bra WL%=;\n"
        "WD%=:\n\t}"
        :: "r"(a), "r"(ph) : "memory");
}

#define LDSM4(r, a) \
    asm volatile("ldmatrix.sync.aligned.m8n8.x4.shared.b16 {%0,%1,%2,%3}, [%4];" \
        : "=r"((r)[0]), "=r"((r)[1]), "=r"((r)[2]), "=r"((r)[3]) : "r"(a))

__device__ __forceinline__ void mma16816(float* d, const uint32_t* a, const uint32_t* b) {
    asm volatile("mma.sync.aligned.m16n8k16.row.col.f32.bf16.bf16.f32 "
        "{%0,%1,%2,%3}, {%4,%5,%6,%7}, {%8,%9}, {%0,%1,%2,%3};"
        : "+f"(d[0]), "+f"(d[1]), "+f"(d[2]), "+f"(d[3])
        : "r"(a[0]), "r"(a[1]), "r"(a[2]), "r"(a[3]), "r"(b[0]), "r"(b[1]));
}

__device__ __forceinline__ float sigmf(float x) { return 1.0f / (1.0f + __expf(-x)); }

// ---------------- init: chunked + swizzled weight builds ----------------
// permuted col n = 16q + 8h + 2a + e  <->  gate (2h+e) of hidden j = 4q + a
__global__ void k_init(const float* __restrict__ W_att, const float* __restrict__ W_ih,
                       const float* __restrict__ W_hh, const float* __restrict__ b_ih,
                       const float* __restrict__ b_hh) {
    long g = (long)blockIdx.x * blockDim.x + threadIdx.x;
    long stride = (long)gridDim.x * blockDim.x;
    for (long i = g; i < (long)NG * KTOT; i += stride) {
        int n = (int)(i / KTOT), k = (int)(i % KTOT);
        int q = n >> 4, r = n & 15;
        int gate = ((r >> 3) << 1) | (r & 1);
        int j = (q << 2) + ((r & 7) >> 1);
        int srow = gate * H_ + j;
        float w = 0.0f;
        if (k < 390)                         w = W_ih[(size_t)srow * 390 + k];
        else if (k >= HOFF && k < HOFF + H_) w = W_hh[(size_t)srow * H_ + (k - HOFF)];
        bf16 hi = __float2bfloat16(w);
        size_t dst = (size_t)(k >> 5) * (NG * 32) + swz(n, k & 31);
        g_Whi[dst] = hi;
        g_Wlo[dst] = __float2bfloat16(w - __bfloat162float(hi));
    }
    for (long i = g; i < (long)NATT * H_; i += stride) {
        int n = (int)(i / H_), k = (int)(i % H_);
        int ks = n >> 7, l = n & 127;
        float w = W_att[(size_t)ks * (H_ * L_) + (size_t)k * L_ + l];
        bf16 hi = __float2bfloat16(w);
        size_t dst = (size_t)(k >> 5) * (NATT * 32) + swz(n, k & 31);
        g_Lhi[dst] = hi;
        g_Llo[dst] = __float2bfloat16(w - __bfloat162float(hi));
    }
    for (long i = g; i < NG; i += stride) {
        int n = (int)i;
        int q = n >> 4, r = n & 15;
        int gate = ((r >> 3) << 1) | (r & 1);
        int j = (q << 2) + ((r & 7) >> 1);
        g_bsum[i] = b_ih[gate * H_ + j] + b_hh[gate * H_ + j];
    }
    bf16 z = __float2bfloat16(0.0f);
    for (long i = g; i < (long)NCHK * B_ * 32; i += stride) {
        g_Ahi0[i] = z; g_Alo0[i] = z; g_Ahi1[i] = z; g_Alo1[i] = z;
    }
    for (long i = g; i < (long)B_ * H_; i += stride) { g_c[i] = 0.0f; g_hmax[i] = -FLT_MAX; }
}

// ---------------- bulk-fed mma.sync GEMM, hi/lo 3-product, fused epilogue ----------------
// A chunked [c][1024][32] starting at chunk CA0; B chunked [c][BROWS][32] chunks 0..NCH-1.
// Warp tile 32 x WN. 3-stage mbarrier ring fed by cp.async.bulk.
template <int BM, int BN, int WN, bool GATES, int BROWS, int NCH, int CA0>
__global__ void __launch_bounds__((BM / 32) * (BN / WN) * 32, 2)
k_mma(const bf16* __restrict__ gAhi, const bf16* __restrict__ gAlo,
      bf16* __restrict__ wAhi, bf16* __restrict__ wAlo,
      const bf16* __restrict__ gBhi, const bf16* __restrict__ gBlo,
      const float* __restrict__ bias) {
    constexpr int NWX = BN / WN, NWY = BM / 32;
    constexpr int NTHR = NWX * NWY * 32;
    constexpr int NB32 = WN / 32;                 // 32-wide N batches per warp
    constexpr uint32_t STAGE_B = (uint32_t)(BM + BN) * 2u * 64u;
    constexpr uint32_t A_BYTES = (uint32_t)BM * 64u;
    constexpr uint32_t B_BYTES = (uint32_t)BN * 64u;
    constexpr uint32_t TXB = 2u * (A_BYTES + B_BYTES);

    extern __shared__ __align__(128) char dyn[];
    __shared__ __align__(8) uint64_t s_mbar[3];
    __shared__ float s_bias[BN];

    const int tid = threadIdx.x, w = tid >> 5, lane = tid & 31;
    const int wx = w % NWX, wy = w / NWX;
    const int m0 = blockIdx.y * BM, n0 = blockIdx.x * BN;
    const uint32_t smb = smem_u32(dyn);
    const uint32_t mb0 = smem_u32(&s_mbar[0]);

    if (tid == 0) { mbar_init(mb0, 1); mbar_init(mb0 + 8, 1); mbar_init(mb0 + 16, 1); }
    for (int i = tid; i < BN; i += NTHR) s_bias[i] = bias[n0 + i];
    __syncthreads();

    // producer: issue stage k into buffer k%3
    auto issue = [&](int k) {
        uint32_t buf = smb + (uint32_t)(k % 3) * STAGE_B;
        uint32_t mb = mb0 + 8u * (k % 3);
        mbar_expect(mb, TXB);
        const char* srcAh = (const char*)gAhi + ((size_t)(CA0 + k) * B_ + m0) * 64;
        const char* srcAl = (const char*)gAlo + ((size_t)(CA0 + k) * B_ + m0) * 64;
        const char* srcBh = (const char*)gBhi + ((size_t)k * BROWS + n0) * 64;
        const char* srcBl = (const char*)gBlo + ((size_t)k * BROWS + n0) * 64;
        bulk_cp(buf,                       srcAh, A_BYTES, mb);
        bulk_cp(buf + A_BYTES,             srcAl, A_BYTES, mb);
        bulk_cp(buf + 2 * A_BYTES,         srcBh, B_BYTES, mb);
        bulk_cp(buf + 2 * A_BYTES + B_BYTES, srcBl, B_BYTES, mb);
    };
    if (tid == 0) { issue(0); issue(1); }

    float acc[2][WN / 8][4];
#pragma unroll
    for (int i = 0; i < 2; i++)
#pragma unroll
        for (int j = 0; j < WN / 8; j++)
#pragma unroll
            for (int k = 0; k < 4; k++) acc[i][j][k] = 0.0f;

    for (int s = 0; s < NCH; s++) {
        if (tid == 0 && s + 2 < NCH) issue(s + 2);
        mbar_wait(mb0 + 8u * (s % 3), (uint32_t)((s / 3) & 1));

        const uint32_t st   = smb + (uint32_t)(s % 3) * STAGE_B;
        const uint32_t stB  = st + 2 * A_BYTES;
#pragma unroll
        for (int ks = 0; ks < 2; ks++) {
            // A fragments: rows wy*32 + mt*16 + (lane&15), k-seg = ks*2 + (lane>>4)
            uint32_t ah[2][4], al[2][4];
#pragma unroll
            for (int mt = 0; mt < 2; mt++) {
                int row = wy * 32 + mt * 16 + (lane & 15);
                int seg = (ks * 2 + (lane >> 4)) ^ ((row + (row >> 2)) & 3);
                uint32_t addr = st + (uint32_t)(row * 64 + (seg & 3) * 16);
                LDSM4(ah[mt], addr);
                LDSM4(al[mt], addr + A_BYTES);
            }
#pragma unroll
            for (int nb32 = 0; nb32 < NB32; nb32++) {
                uint32_t bh[2][4], bl[2][4];
#pragma unroll
                for (int nb = 0; nb < 2; nb++) {
                    int gg = lane >> 3;
                    int row = wx * WN + nb32 * 32 + nb * 16 + ((gg >> 1) << 3) + (lane & 7);
                    int seg = (ks * 2 + (gg & 1)) ^ ((row + (row >> 2)) & 3);
                    uint32_t addr = stB + (uint32_t)(row * 64 + (seg & 3) * 16);
                    LDSM4(bh[nb], addr);
                    LDSM4(bl[nb], addr + B_BYTES);
                }
#pragma unroll
                for (int mt = 0; mt < 2; mt++)
#pragma unroll
                    for (int j2 = 0; j2 < 4; j2++) {
                        float* a = acc[mt][nb32 * 4 + j2];
                        const uint32_t* ph = &bh[j2 >> 1][(j2 & 1) * 2];
                        const uint32_t* pl = &bl[j2 >> 1][(j2 & 1) * 2];
                        mma16816(a, ah[mt], ph);
                        mma16816(a, ah[mt], pl);
                        mma16816(a, al[mt], ph);
                    }
            }
        }
        __syncthreads();
    }

    const int a_ = lane & 3, rl = lane >> 2;
    if constexpr (GATES) {
#pragma unroll
        for (int mt = 0; mt < 2; mt++)
#pragma unroll
            for (int p = 0; p < WN / 16; p++) {
                const int colb = wx * WN + p * 16;
                const float bi = s_bias[colb + 2 * a_];
                const float bf = s_bias[colb + 2 * a_ + 1];
                const float bg = s_bias[colb + 8 + 2 * a_];
                const float bo = s_bias[colb + 8 + 2 * a_ + 1];
                const int j = ((n0 + colb) >> 2) + a_;
#pragma unroll
                for (int rh = 0; rh < 2; rh++) {
                    float iv = acc[mt][2 * p][2 * rh]     + bi;
                    float fv = acc[mt][2 * p][2 * rh + 1] + bf;
                    float gv = acc[mt][2 * p + 1][2 * rh]     + bg;
                    float ov = acc[mt][2 * p + 1][2 * rh + 1] + bo;
                    int b = m0 + wy * 32 + mt * 16 + rh * 8 + rl;
                    size_t cidx = (size_t)b * H_ + j;
                    float c = sigmf(fv) * g_c[cidx] + sigmf(iv) * tanhf(gv);
                    float h = sigmf(ov) * tanhf(c);
                    g_c[cidx] = c;
                    g_hmax[cidx] = fmaxf(g_hmax[cidx], h);
                    bf16 hh = __float2bfloat16(h);
                    size_t widx = (size_t)(13 + (j >> 5)) * (B_ * 32) + swz(b, j & 31);
                    wAhi[widx] = hh;
                    wAlo[widx] = __float2bfloat16(h - __bfloat162float(hh));
                }
            }
    } else {
#pragma unroll
        for (int mt = 0; mt < 2; mt++)
#pragma unroll
            for (int nt = 0; nt < WN / 8; nt++) {
                const int lc = wx * WN + nt * 8 + 2 * a_;
#pragma unroll
                for (int rh = 0; rh < 2; rh++) {
                    int row = m0 + wy * 32 + mt * 16 + rh * 8 + rl;
                    float2 v;
                    v.x = acc[mt][nt][2 * rh]     + s_bias[lc];
                    v.y = acc[mt][nt][2 * rh + 1] + s_bias[lc + 1];
                    *(float2*)&g_logits[(size_t)row * NATT + n0 + lc] = v;
                }
            }
    }
}

// ---------------- fused softmax + attention pooling (writes v chunked hi/lo) ----------------
__global__ void k_attn(const float* __restrict__ X, bf16* __restrict__ wHi,
                       bf16* __restrict__ wLo) {
    __shared__ float alp[NATT];
    __shared__ float xs[16 * DIN];
    __shared__ float red[16];
    const int b = blockIdx.x;
    const int tid = threadIdx.x;
    for (int i = tid; i < NATT; i += 416) alp[i] = g_logits[b * NATT + i];
    __syncthreads();

    const int wid = tid >> 5, lane = tid & 31;
    float xv = (tid < NATT) ? alp[tid] : -FLT_MAX;
    float m = xv;
#pragma unroll
    for (int off = 16; off; off >>= 1) m = fmaxf(m, __shfl_xor_sync(0xffffffffu, m, off));
    if (lane == 0) red[wid] = m;
    __syncthreads();
    if (tid < NATT) {
        int k4 = (tid >> 7) << 2;
        float rm = fmaxf(fmaxf(red[k4], red[k4 + 1]), fmaxf(red[k4 + 2], red[k4 + 3]));
        xv = expf(xv - rm);
    } else xv = 0.0f;
    __syncthreads();
    float s = xv;
#pragma unroll
    for (int off = 16; off; off >>= 1) s += __shfl_xor_sync(0xffffffffu, s, off);
    if (lane == 0) red[wid] = s;
    __syncthreads();
    if (tid < NATT) {
        int k4 = (tid >> 7) << 2;
        float rs = red[k4] + red[k4 + 1] + red[k4 + 2] + red[k4 + 3];
        alp[tid] = xv / rs;
    }
    __syncthreads();

    float acc = 0.0f;
    const int k = tid / DIN, d = tid - k * DIN;
    const float* Xb = X + (size_t)b * (L_ * DIN);
    for (int lc = 0; lc < L_; lc += 16) {
        for (int i = tid; i < 16 * DIN; i += 416) xs[i] = Xb[lc * DIN + i];
        __syncthreads();
        if (tid < 390) {
#pragma unroll
            for (int l = 0; l < 16; l++) acc += alp[k * L_ + lc + l] * xs[l * DIN + d];
        }
        __syncthreads();
    }
    if (tid < 390) {
        bf16 hi = __float2bfloat16(acc);
        size_t off = (size_t)(tid >> 5) * (B_ * 32) + swz(b, tid & 31);
        wHi[off] = hi;
        wLo[off] = __float2bfloat16(acc - __bfloat162float(hi));
    }
}

// ---------------- fused tail ----------------
__global__ void k_tail(const float* __restrict__ Fe, const float* __restrict__ W_d1,
                       const float* __restrict__ b_d1, const float* __restrict__ W_r,
                       const float* __restrict__ b_r, const float* __restrict__ W_a,
                       const float* __restrict__ W_d2, const float* __restrict__ b_d2,
                       float* __restrict__ out) {
    __shared__ float hs[H_];
    __shared__ float yb[FEAT_];
    __shared__ float r1[PROJ_], r2[PROJ_], sb[PROJ_];
    __shared__ float aw[2];
    const int b = blockIdx.x, tid = threadIdx.x;   // 64 threads
    for (int i = tid; i < H_; i += 64) hs[i] = g_hmax[(size_t)b * H_ + i];
    __syncthreads();
    if (tid < FEAT_) {
        float a = b_d1[tid];
        const float* w = W_d1 + tid * H_;
        for (int k2 = 0; k2 < H_; k2++) a += hs[k2] * w[k2];
        yb[tid] = fmaxf(a, 0.0f);
    }
    __syncthreads();
    if (tid < PROJ_) {
        float a = b_r[tid], a2 = b_r[tid];
        const float* w = W_r + tid * FEAT_;
        const float* fe = Fe + b * FEAT_;
        for (int q = 0; q < FEAT_; q++) { a += yb[q] * w[q]; a2 += fe[q] * w[q]; }
        r1[tid] = a  > 0.0f ? a  : 0.01f * a;
        r2[tid] = a2 > 0.0f ? a2 : 0.01f * a2;
    }
    __syncthreads();
    if (tid == 0) {
        float s1 = 0.0f, s2 = 0.0f;
        for (int p = 0; p < PROJ_; p++) { s1 += tanhf(r1[p]) * W_a[p]; s2 += tanhf(r2[p]) * W_a[p]; }
        float mx = fmaxf(s1, s2);
        float e1 = expf(s1 - mx), e2 = expf(s2 - mx);
        float inv = 1.0f / (e1 + e2);
        aw[0] = e1 * inv; aw[1] = e2 * inv;
    }
    __syncthreads();
    if (tid < PROJ_) sb[tid] = fmaxf(aw[0] * r1[tid] + aw[1] * r2[tid], 0.0f);
    __syncthreads();
    if (tid < 2) {
        float a = b_d2[tid];
        const float* w = W_d2 + tid * PROJ_;
        for (int p = 0; p < PROJ_; p++) a += sb[p] * w[p];
        out[b * 2 + tid] = a;
    }
}

// ---------------- launch ----------------
extern "C" void kernel_launch(void* const* d_in, const int* in_sizes, int n_in,
                              void* d_out, int out_size) {
    const float* X     = (const float*)d_in[0];
    const float* Fe    = (const float*)d_in[1];
    const float* W_att = (const float*)d_in[2];
    const float* b_att = (const float*)d_in[3];
    const float* W_ih  = (const float*)d_in[4];
    const float* W_hh  = (const float*)d_in[5];
    const float* b_ih  = (const float*)d_in[6];
    const float* b_hh  = (const float*)d_in[7];
    const float* W_d1  = (const float*)d_in[8];
    const float* b_d1  = (const float*)d_in[9];
    const float* W_r   = (const float*)d_in[10];
    const float* b_r   = (const float*)d_in[11];
    const float* W_a   = (const float*)d_in[12];
    const float* W_d2  = (const float*)d_in[13];
    const float* b_d2  = (const float*)d_in[14];
    float* out = (float*)d_out;

    bf16 *Ah0, *Al0, *Ah1, *Al1, *Whi, *Wlo, *Lhi, *Llo;
    float *bsum;
    cudaGetSymbolAddress((void**)&Ah0, g_Ahi0);
    cudaGetSymbolAddress((void**)&Al0, g_Alo0);
    cudaGetSymbolAddress((void**)&Ah1, g_Ahi1);
    cudaGetSymbolAddress((void**)&Al1, g_Alo1);
    cudaGetSymbolAddress((void**)&Whi, g_Whi);
    cudaGetSymbolAddress((void**)&Wlo, g_Wlo);
    cudaGetSymbolAddress((void**)&Lhi, g_Lhi);
    cudaGetSymbolAddress((void**)&Llo, g_Llo);
    cudaGetSymbolAddress((void**)&bsum, g_bsum);

    constexpr int DSMEM_G = 3 * (128 + 128) * 2 * 64;   // 98304 B
    constexpr int DSMEM_L = 3 * (64 + 64) * 2 * 64;     // 49152 B
    cudaFuncSetAttribute((const void*)k_mma<128, 128, 64, true,  NG,   37, 0>,
                         cudaFuncAttributeMaxDynamicSharedMemorySize, DSMEM_G);
    cudaFuncSetAttribute((const void*)k_mma<64, 64, 32, false, NATT, 24, 13>,
                         cudaFuncAttributeMaxDynamicSharedMemorySize, DSMEM_L);

    k_init<<<2048, 256>>>(W_att, W_ih, W_hh, b_ih, b_hh);

    for (int t = 0; t < L_; t++) {
        bf16* rdHi = (t & 1) ? Ah1 : Ah0;
        bf16* rdLo = (t & 1) ? Al1 : Al0;
        bf16* wrHi = (t & 1) ? Ah0 : Ah1;
        bf16* wrLo = (t & 1) ? Al0 : Al1;
        // logits[1024,384] = h @ Wl + b_att   (A chunks 13..36)
        k_mma<64, 64, 32, false, NATT, 24, 13><<<dim3(NATT / 64, B_ / 64), 128, DSMEM_L>>>(
            rdHi, rdLo, nullptr, nullptr, Lhi, Llo, b_att);
        // softmax + attention pooling -> v chunks 0..12 of rd buffer
        k_attn<<<B_, 416>>>(X, rdHi, rdLo);
        // gates = [v|h] @ Wcat + bsum, fused LSTM cell -> h into wr buffer
        k_mma<128, 128, 64, true, NG, 37, 0><<<dim3(NG / 128, B_ / 128), 256, DSMEM_G>>>(
            rdHi, rdLo, wrHi, wrLo, Whi, Wlo, bsum);
    }

    k_tail<<<B_, 64>>>(Fe, W_d1, b_d1, W_r, b_r, W_a, W_d2, b_d2, out);
}

// round 8
// speedup vs baseline: 2.4490x; 1.0001x over previous
#include <cuda_runtime.h>
#include <cuda_bf16.h>
#include <math.h>
#include <float.h>
#include <stdint.h>

#define B_    1024
#define L_    128
#define DIN   130
#define H_    768
#define FEAT_ 49
#define PROJ_ 40
#define NG    3072          // 4*H
#define NATT  384           // 3*L
#define NCHK  37            // total K chunks of 32: v chunks 0..12, h chunks 13..36
#define HOFF  416           // h starts at k=416 (chunk 13)
#define KTOT  1184

typedef __nv_bfloat16 bf16;

// ---------------- device scratch (chunked, swizzled layouts) ----------------
// A: [chunk][1024 rows][32 k]  (bf16), swizzled within each row's 64B
__device__ bf16 g_Ahi0[NCHK*B_*32], g_Alo0[NCHK*B_*32];
__device__ bf16 g_Ahi1[NCHK*B_*32], g_Alo1[NCHK*B_*32];
__device__ bf16 g_Whi[NCHK*NG*32],  g_Wlo[NCHK*NG*32];   // gates W^T chunked [c][n_perm][32]
__device__ bf16 g_Lhi[24*NATT*32],  g_Llo[24*NATT*32];   // logits W^T chunked [c][n][32]
__device__ float g_bsum[NG];
__device__ float g_c[B_*H_], g_hmax[B_*H_];
__device__ float g_logits[B_*NATT];

// ---------------- helpers ----------------
__device__ __forceinline__ uint32_t smem_u32(const void* p) {
    return (uint32_t)__cvta_generic_to_shared(p);
}
// element offset inside one chunk block for (row, kk): 64B rows, XOR seg swizzle
__device__ __forceinline__ int swz(int row, int kk) {
    int seg = ((kk >> 3) ^ (row + (row >> 2))) & 3;
    return row * 32 + seg * 8 + (kk & 7);
}
__device__ __forceinline__ void bulk_cp(uint32_t dst, const void* src, uint32_t bytes,
                                        uint32_t mbar) {
    asm volatile("cp.async.bulk.shared::cluster.global.mbarrier::complete_tx::bytes "
                 "[%0], [%1], %2, [%3];"
                 :: "r"(dst), "l"(__cvta_generic_to_global(src)), "r"(bytes), "r"(mbar)
                 : "memory");
}
__device__ __forceinline__ void mbar_init(uint32_t a, uint32_t cnt) {
    asm volatile("mbarrier.init.shared.b64 [%0], %1;" :: "r"(a), "r"(cnt) : "memory");
}
__device__ __forceinline__ void mbar_expect(uint32_t a, uint32_t tx) {
    asm volatile("mbarrier.arrive.expect_tx.shared.b64 _, [%0], %1;"
                 :: "r"(a), "r"(tx) : "memory");
}
__device__ __forceinline__ void mbar_wait(uint32_t a, uint32_t ph) {
    asm volatile(
        "{\n\t.reg .pred P;\n"
        "WL%=:\n\t"
        "mbarrier.try_wait.parity.acquire.cta.shared::cta.b64 P, [%0], %1, 0x989680;\n\t"
        "@P bra WD%=;\n\t"
        "bra WL%=;\n"
        "WD%=:\n\t}"
        :: "r"(a), "r"(ph) : "memory");
}

#define LDSM4(r, a) \
    asm volatile("ldmatrix.sync.aligned.m8n8.x4.shared.b16 {%0,%1,%2,%3}, [%4];" \
        : "=r"((r)[0]), "=r"((r)[1]), "=r"((r)[2]), "=r"((r)[3]) : "r"(a))

__device__ __forceinline__ void mma16816(float* d, const uint32_t* a, const uint32_t* b) {
    asm volatile("mma.sync.aligned.m16n8k16.row.col.f32.bf16.bf16.f32 "
        "{%0,%1,%2,%3}, {%4,%5,%6,%7}, {%8,%9}, {%0,%1,%2,%3};"
        : "+f"(d[0]), "+f"(d[1]), "+f"(d[2]), "+f"(d[3])
        : "r"(a[0]), "r"(a[1]), "r"(a[2]), "r"(a[3]), "r"(b[0]), "r"(b[1]));
}

__device__ __forceinline__ float sigmf(float x) { return 1.0f / (1.0f + __expf(-x)); }

// ---------------- init: chunked + swizzled weight builds ----------------
// permuted col n = 16q + 8h + 2a + e  <->  gate (2h+e) of hidden j = 4q + a
__global__ void k_init(const float* __restrict__ W_att, const float* __restrict__ W_ih,
                       const float* __restrict__ W_hh, const float* __restrict__ b_ih,
                       const float* __restrict__ b_hh) {
    long g = (long)blockIdx.x * blockDim.x + threadIdx.x;
    long stride = (long)gridDim.x * blockDim.x;
    for (long i = g; i < (long)NG * KTOT; i += stride) {
        int n = (int)(i / KTOT), k = (int)(i % KTOT);
        int q = n >> 4, r = n & 15;
        int gate = ((r >> 3) << 1) | (r & 1);
        int j = (q << 2) + ((r & 7) >> 1);
        int srow = gate * H_ + j;
        float w = 0.0f;
        if (k < 390)                         w = W_ih[(size_t)srow * 390 + k];
        else if (k >= HOFF && k < HOFF + H_) w = W_hh[(size_t)srow * H_ + (k - HOFF)];
        bf16 hi = __float2bfloat16(w);
        size_t dst = (size_t)(k >> 5) * (NG * 32) + swz(n, k & 31);
        g_Whi[dst] = hi;
        g_Wlo[dst] = __float2bfloat16(w - __bfloat162float(hi));
    }
    for (long i = g; i < (long)NATT * H_; i += stride) {
        int n = (int)(i / H_), k = (int)(i % H_);
        int ks = n >> 7, l = n & 127;
        float w = W_att[(size_t)ks * (H_ * L_) + (size_t)k * L_ + l];
        bf16 hi = __float2bfloat16(w);
        size_t dst = (size_t)(k >> 5) * (NATT * 32) + swz(n, k & 31);
        g_Lhi[dst] = hi;
        g_Llo[dst] = __float2bfloat16(w - __bfloat162float(hi));
    }
    for (long i = g; i < NG; i += stride) {
        int n = (int)i;
        int q = n >> 4, r = n & 15;
        int gate = ((r >> 3) << 1) | (r & 1);
        int j = (q << 2) + ((r & 7) >> 1);
        g_bsum[i] = b_ih[gate * H_ + j] + b_hh[gate * H_ + j];
    }
    bf16 z = __float2bfloat16(0.0f);
    for (long i = g; i < (long)NCHK * B_ * 32; i += stride) {
        g_Ahi0[i] = z; g_Alo0[i] = z; g_Ahi1[i] = z; g_Alo1[i] = z;
    }
    for (long i = g; i < (long)B_ * H_; i += stride) { g_c[i] = 0.0f; g_hmax[i] = -FLT_MAX; }
}

// ---------------- bulk-fed mma.sync GEMM, hi/lo 3-product, fused epilogue ----------------
// A chunked [c][1024][32] starting at chunk CA0; B chunked [c][BROWS][32] chunks 0..NCH-1.
// Warp tile 32 x WN. 3-stage mbarrier ring fed by cp.async.bulk.
template <int BM, int BN, int WN, bool GATES, int BROWS, int NCH, int CA0>
__global__ void __launch_bounds__((BM / 32) * (BN / WN) * 32, 2)
k_mma(const bf16* __restrict__ gAhi, const bf16* __restrict__ gAlo,
      bf16* __restrict__ wAhi, bf16* __restrict__ wAlo,
      const bf16* __restrict__ gBhi, const bf16* __restrict__ gBlo,
      const float* __restrict__ bias) {
    constexpr int NWX = BN / WN, NWY = BM / 32;
    constexpr int NTHR = NWX * NWY * 32;
    constexpr int NB32 = WN / 32;                 // 32-wide N batches per warp
    constexpr uint32_t STAGE_B = (uint32_t)(BM + BN) * 2u * 64u;
    constexpr uint32_t A_BYTES = (uint32_t)BM * 64u;
    constexpr uint32_t B_BYTES = (uint32_t)BN * 64u;
    constexpr uint32_t TXB = 2u * (A_BYTES + B_BYTES);

    extern __shared__ __align__(128) char dyn[];
    __shared__ __align__(8) uint64_t s_mbar[3];
    __shared__ float s_bias[BN];

    const int tid = threadIdx.x, w = tid >> 5, lane = tid & 31;
    const int wx = w % NWX, wy = w / NWX;
    const int m0 = blockIdx.y * BM, n0 = blockIdx.x * BN;
    const uint32_t smb = smem_u32(dyn);
    const uint32_t mb0 = smem_u32(&s_mbar[0]);

    if (tid == 0) { mbar_init(mb0, 1); mbar_init(mb0 + 8, 1); mbar_init(mb0 + 16, 1); }
    for (int i = tid; i < BN; i += NTHR) s_bias[i] = bias[n0 + i];
    __syncthreads();

    // producer: issue stage k into buffer k%3
    auto issue = [&](int k) {
        uint32_t buf = smb + (uint32_t)(k % 3) * STAGE_B;
        uint32_t mb = mb0 + 8u * (k % 3);
        mbar_expect(mb, TXB);
        const char* srcAh = (const char*)gAhi + ((size_t)(CA0 + k) * B_ + m0) * 64;
        const char* srcAl = (const char*)gAlo + ((size_t)(CA0 + k) * B_ + m0) * 64;
        const char* srcBh = (const char*)gBhi + ((size_t)k * BROWS + n0) * 64;
        const char* srcBl = (const char*)gBlo + ((size_t)k * BROWS + n0) * 64;
        bulk_cp(buf,                       srcAh, A_BYTES, mb);
        bulk_cp(buf + A_BYTES,             srcAl, A_BYTES, mb);
        bulk_cp(buf + 2 * A_BYTES,         srcBh, B_BYTES, mb);
        bulk_cp(buf + 2 * A_BYTES + B_BYTES, srcBl, B_BYTES, mb);
    };
    if (tid == 0) { issue(0); issue(1); }

    float acc[2][WN / 8][4];
#pragma unroll
    for (int i = 0; i < 2; i++)
#pragma unroll
        for (int j = 0; j < WN / 8; j++)
#pragma unroll
            for (int k = 0; k < 4; k++) acc[i][j][k] = 0.0f;

    for (int s = 0; s < NCH; s++) {
        if (tid == 0 && s + 2 < NCH) issue(s + 2);
        mbar_wait(mb0 + 8u * (s % 3), (uint32_t)((s / 3) & 1));

        const uint32_t st   = smb + (uint32_t)(s % 3) * STAGE_B;
        const uint32_t stB  = st + 2 * A_BYTES;
#pragma unroll
        for (int ks = 0; ks < 2; ks++) {
            // A fragments: rows wy*32 + mt*16 + (lane&15), k-seg = ks*2 + (lane>>4)
            uint32_t ah[2][4], al[2][4];
#pragma unroll
            for (int mt = 0; mt < 2; mt++) {
                int row = wy * 32 + mt * 16 + (lane & 15);
                int seg = (ks * 2 + (lane >> 4)) ^ ((row + (row >> 2)) & 3);
                uint32_t addr = st + (uint32_t)(row * 64 + (seg & 3) * 16);
                LDSM4(ah[mt], addr);
                LDSM4(al[mt], addr + A_BYTES);
            }
#pragma unroll
            for (int nb32 = 0; nb32 < NB32; nb32++) {
                uint32_t bh[2][4], bl[2][4];
#pragma unroll
                for (int nb = 0; nb < 2; nb++) {
                    int gg = lane >> 3;
                    int row = wx * WN + nb32 * 32 + nb * 16 + ((gg >> 1) << 3) + (lane & 7);
                    int seg = (ks * 2 + (gg & 1)) ^ ((row + (row >> 2)) & 3);
                    uint32_t addr = stB + (uint32_t)(row * 64 + (seg & 3) * 16);
                    LDSM4(bh[nb], addr);
                    LDSM4(bl[nb], addr + B_BYTES);
                }
#pragma unroll
                for (int mt = 0; mt < 2; mt++)
#pragma unroll
                    for (int j2 = 0; j2 < 4; j2++) {
                        float* a = acc[mt][nb32 * 4 + j2];
                        const uint32_t* ph = &bh[j2 >> 1][(j2 & 1) * 2];
                        const uint32_t* pl = &bl[j2 >> 1][(j2 & 1) * 2];
                        mma16816(a, ah[mt], ph);
                        mma16816(a, ah[mt], pl);
                        mma16816(a, al[mt], ph);
                    }
            }
        }
        __syncthreads();
    }

    const int a_ = lane & 3, rl = lane >> 2;
    if constexpr (GATES) {
#pragma unroll
        for (int mt = 0; mt < 2; mt++)
#pragma unroll
            for (int p = 0; p < WN / 16; p++) {
                const int colb = wx * WN + p * 16;
                const float bi = s_bias[colb + 2 * a_];
                const float bf = s_bias[colb + 2 * a_ + 1];
                const float bg = s_bias[colb + 8 + 2 * a_];
                const float bo = s_bias[colb + 8 + 2 * a_ + 1];
                const int j = ((n0 + colb) >> 2) + a_;
#pragma unroll
                for (int rh = 0; rh < 2; rh++) {
                    float iv = acc[mt][2 * p][2 * rh]     + bi;
                    float fv = acc[mt][2 * p][2 * rh + 1] + bf;
                    float gv = acc[mt][2 * p + 1][2 * rh]     + bg;
                    float ov = acc[mt][2 * p + 1][2 * rh + 1] + bo;
                    int b = m0 + wy * 32 + mt * 16 + rh * 8 + rl;
                    size_t cidx = (size_t)b * H_ + j;
                    float c = sigmf(fv) * g_c[cidx] + sigmf(iv) * tanhf(gv);
                    float h = sigmf(ov) * tanhf(c);
                    g_c[cidx] = c;
                    g_hmax[cidx] = fmaxf(g_hmax[cidx], h);
                    bf16 hh = __float2bfloat16(h);
                    size_t widx = (size_t)(13 + (j >> 5)) * (B_ * 32) + swz(b, j & 31);
                    wAhi[widx] = hh;
                    wAlo[widx] = __float2bfloat16(h - __bfloat162float(hh));
                }
            }
    } else {
#pragma unroll
        for (int mt = 0; mt < 2; mt++)
#pragma unroll
            for (int nt = 0; nt < WN / 8; nt++) {
                const int lc = wx * WN + nt * 8 + 2 * a_;
#pragma unroll
                for (int rh = 0; rh < 2; rh++) {
                    int row = m0 + wy * 32 + mt * 16 + rh * 8 + rl;
                    float2 v;
                    v.x = acc[mt][nt][2 * rh]     + s_bias[lc];
                    v.y = acc[mt][nt][2 * rh + 1] + s_bias[lc + 1];
                    *(float2*)&g_logits[(size_t)row * NATT + n0 + lc] = v;
                }
            }
    }
}

// ---------------- fused softmax + attention pooling (writes v chunked hi/lo) ----------------
__global__ void k_attn(const float* __restrict__ X, bf16* __restrict__ wHi,
                       bf16* __restrict__ wLo) {
    __shared__ float alp[NATT];
    __shared__ float xs[16 * DIN];
    __shared__ float red[16];
    const int b = blockIdx.x;
    const int tid = threadIdx.x;
    for (int i = tid; i < NATT; i += 416) alp[i] = g_logits[b * NATT + i];
    __syncthreads();

    const int wid = tid >> 5, lane = tid & 31;
    float xv = (tid < NATT) ? alp[tid] : -FLT_MAX;
    float m = xv;
#pragma unroll
    for (int off = 16; off; off >>= 1) m = fmaxf(m, __shfl_xor_sync(0xffffffffu, m, off));
    if (lane == 0) red[wid] = m;
    __syncthreads();
    if (tid < NATT) {
        int k4 = (tid >> 7) << 2;
        float rm = fmaxf(fmaxf(red[k4], red[k4 + 1]), fmaxf(red[k4 + 2], red[k4 + 3]));
        xv = expf(xv - rm);
    } else xv = 0.0f;
    __syncthreads();
    float s = xv;
#pragma unroll
    for (int off = 16; off; off >>= 1) s += __shfl_xor_sync(0xffffffffu, s, off);
    if (lane == 0) red[wid] = s;
    __syncthreads();
    if (tid < NATT) {
        int k4 = (tid >> 7) << 2;
        float rs = red[k4] + red[k4 + 1] + red[k4 + 2] + red[k4 + 3];
        alp[tid] = xv / rs;
    }
    __syncthreads();

    float acc = 0.0f;
    const int k = tid / DIN, d = tid - k * DIN;
    const float* Xb = X + (size_t)b * (L_ * DIN);
    for (int lc = 0; lc < L_; lc += 16) {
        for (int i = tid; i < 16 * DIN; i += 416) xs[i] = Xb[lc * DIN + i];
        __syncthreads();
        if (tid < 390) {
#pragma unroll
            for (int l = 0; l < 16; l++) acc += alp[k * L_ + lc + l] * xs[l * DIN + d];
        }
        __syncthreads();
    }
    if (tid < 390) {
        bf16 hi = __float2bfloat16(acc);
        size_t off = (size_t)(tid >> 5) * (B_ * 32) + swz(b, tid & 31);
        wHi[off] = hi;
        wLo[off] = __float2bfloat16(acc - __bfloat162float(hi));
    }
}

// ---------------- fused tail ----------------
__global__ void k_tail(const float* __restrict__ Fe, const float* __restrict__ W_d1,
                       const float* __restrict__ b_d1, const float* __restrict__ W_r,
                       const float* __restrict__ b_r, const float* __restrict__ W_a,
                       const float* __restrict__ W_d2, const float* __restrict__ b_d2,
                       float* __restrict__ out) {
    __shared__ float hs[H_];
    __shared__ float yb[FEAT_];
    __shared__ float r1[PROJ_], r2[PROJ_], sb[PROJ_];
    __shared__ float aw[2];
    const int b = blockIdx.x, tid = threadIdx.x;   // 64 threads
    for (int i = tid; i < H_; i += 64) hs[i] = g_hmax[(size_t)b * H_ + i];
    __syncthreads();
    if (tid < FEAT_) {
        float a = b_d1[tid];
        const float* w = W_d1 + tid * H_;
        for (int k2 = 0; k2 < H_; k2++) a += hs[k2] * w[k2];
        yb[tid] = fmaxf(a, 0.0f);
    }
    __syncthreads();
    if (tid < PROJ_) {
        float a = b_r[tid], a2 = b_r[tid];
        const float* w = W_r + tid * FEAT_;
        const float* fe = Fe + b * FEAT_;
        for (int q = 0; q < FEAT_; q++) { a += yb[q] * w[q]; a2 += fe[q] * w[q]; }
        r1[tid] = a  > 0.0f ? a  : 0.01f * a;
        r2[tid] = a2 > 0.0f ? a2 : 0.01f * a2;
    }
    __syncthreads();
    if (tid == 0) {
        float s1 = 0.0f, s2 = 0.0f;
        for (int p = 0; p < PROJ_; p++) { s1 += tanhf(r1[p]) * W_a[p]; s2 += tanhf(r2[p]) * W_a[p]; }
        float mx = fmaxf(s1, s2);
        float e1 = expf(s1 - mx), e2 = expf(s2 - mx);
        float inv = 1.0f / (e1 + e2);
        aw[0] = e1 * inv; aw[1] = e2 * inv;
    }
    __syncthreads();
    if (tid < PROJ_) sb[tid] = fmaxf(aw[0] * r1[tid] + aw[1] * r2[tid], 0.0f);
    __syncthreads();
    if (tid < 2) {
        float a = b_d2[tid];
        const float* w = W_d2 + tid * PROJ_;
        for (int p = 0; p < PROJ_; p++) a += sb[p] * w[p];
        out[b * 2 + tid] = a;
    }
}

// ---------------- launch ----------------
extern "C" void kernel_launch(void* const* d_in, const int* in_sizes, int n_in,
                              void* d_out, int out_size) {
    const float* X     = (const float*)d_in[0];
    const float* Fe    = (const float*)d_in[1];
    const float* W_att = (const float*)d_in[2];
    const float* b_att = (const float*)d_in[3];
    const float* W_ih  = (const float*)d_in[4];
    const float* W_hh  = (const float*)d_in[5];
    const float* b_ih  = (const float*)d_in[6];
    const float* b_hh  = (const float*)d_in[7];
    const float* W_d1  = (const float*)d_in[8];
    const float* b_d1  = (const float*)d_in[9];
    const float* W_r   = (const float*)d_in[10];
    const float* b_r   = (const float*)d_in[11];
    const float* W_a   = (const float*)d_in[12];
    const float* W_d2  = (const float*)d_in[13];
    const float* b_d2  = (const float*)d_in[14];
    float* out = (float*)d_out;

    bf16 *Ah0, *Al0, *Ah1, *Al1, *Whi, *Wlo, *Lhi, *Llo;
    float *bsum;
    cudaGetSymbolAddress((void**)&Ah0, g_Ahi0);
    cudaGetSymbolAddress((void**)&Al0, g_Alo0);
    cudaGetSymbolAddress((void**)&Ah1, g_Ahi1);
    cudaGetSymbolAddress((void**)&Al1, g_Alo1);
    cudaGetSymbolAddress((void**)&Whi, g_Whi);
    cudaGetSymbolAddress((void**)&Wlo, g_Wlo);
    cudaGetSymbolAddress((void**)&Lhi, g_Lhi);
    cudaGetSymbolAddress((void**)&Llo, g_Llo);
    cudaGetSymbolAddress((void**)&bsum, g_bsum);

    constexpr int DSMEM_G = 3 * (128 + 128) * 2 * 64;   // 98304 B
    constexpr int DSMEM_L = 3 * (64 + 64) * 2 * 64;     // 49152 B
    cudaFuncSetAttribute((const void*)k_mma<128, 128, 64, true,  NG,   37, 0>,
                         cudaFuncAttributeMaxDynamicSharedMemorySize, DSMEM_G);
    cudaFuncSetAttribute((const void*)k_mma<64, 64, 32, false, NATT, 24, 13>,
                         cudaFuncAttributeMaxDynamicSharedMemorySize, DSMEM_L);

    k_init<<<2048, 256>>>(W_att, W_ih, W_hh, b_ih, b_hh);

    for (int t = 0; t < L_; t++) {
        bf16* rdHi = (t & 1) ? Ah1 : Ah0;
        bf16* rdLo = (t & 1) ? Al1 : Al0;
        bf16* wrHi = (t & 1) ? Ah0 : Ah1;
        bf16* wrLo = (t & 1) ? Al0 : Al1;
        // logits[1024,384] = h @ Wl + b_att   (A chunks 13..36)
        k_mma<64, 64, 32, false, NATT, 24, 13><<<dim3(NATT / 64, B_ / 64), 128, DSMEM_L>>>(
            rdHi, rdLo, nullptr, nullptr, Lhi, Llo, b_att);
        // softmax + attention pooling -> v chunks 0..12 of rd buffer
        k_attn<<<B_, 416>>>(X, rdHi, rdLo);
        // gates = [v|h] @ Wcat + bsum, fused LSTM cell -> h into wr buffer
        k_mma<128, 128, 64, true, NG, 37, 0><<<dim3(NG / 128, B_ / 128), 256, DSMEM_G>>>(
            rdHi, rdLo, wrHi, wrLo, Whi, Wlo, bsum);
    }

    k_tail<<<B_, 64>>>(Fe, W_d1, b_d1, W_r, b_r, W_a, W_d2, b_d2, out);
}

// round 9
// speedup vs baseline: 2.6467x; 1.0807x over previous
#include <cuda_runtime.h>
#include <cuda_bf16.h>
#include <math.h>
#include <float.h>
#include <stdint.h>

#define B_    1024
#define L_    128
#define DIN   130
#define H_    768
#define FEAT_ 49
#define PROJ_ 40
#define NG    3072          // 4*H
#define NATT  384           // 3*L
#define NCHK  37            // total K chunks of 32: v chunks 0..12, h chunks 13..36
#define HOFF  416           // h starts at k=416 (chunk 13)
#define KTOT  1184

typedef __nv_bfloat16 bf16;

// ---------------- device scratch (chunked, swizzled layouts) ----------------
__device__ bf16 g_Ahi0[NCHK*B_*32], g_Alo0[NCHK*B_*32];
__device__ bf16 g_Ahi1[NCHK*B_*32], g_Alo1[NCHK*B_*32];
__device__ bf16 g_Whi[NCHK*NG*32],  g_Wlo[NCHK*NG*32];   // gates W^T chunked [c][n_perm][32]
__device__ bf16 g_Lhi[24*NATT*32],  g_Llo[24*NATT*32];   // logits W^T chunked [c][n][32]
__device__ float g_bsum[NG];
__device__ float g_c[B_*H_], g_hmax[B_*H_];
__device__ float g_logits[B_*NATT];

// ---------------- helpers ----------------
__device__ __forceinline__ uint32_t smem_u32(const void* p) {
    return (uint32_t)__cvta_generic_to_shared(p);
}
__device__ __forceinline__ int swz(int row, int kk) {
    int seg = ((kk >> 3) ^ (row + (row >> 2))) & 3;
    return row * 32 + seg * 8 + (kk & 7);
}
__device__ __forceinline__ void bulk_cp(uint32_t dst, const void* src, uint32_t bytes,
                                        uint32_t mbar) {
    asm volatile("cp.async.bulk.shared::cluster.global.mbarrier::complete_tx::bytes "
                 "[%0], [%1], %2, [%3];"
                 :: "r"(dst), "l"(__cvta_generic_to_global(src)), "r"(bytes), "r"(mbar)
                 : "memory");
}
__device__ __forceinline__ void mbar_init(uint32_t a, uint32_t cnt) {
    asm volatile("mbarrier.init.shared.b64 [%0], %1;" :: "r"(a), "r"(cnt) : "memory");
}
__device__ __forceinline__ void mbar_expect(uint32_t a, uint32_t tx) {
    asm volatile("mbarrier.arrive.expect_tx.shared.b64 _, [%0], %1;"
                 :: "r"(a), "r"(tx) : "memory");
}
__device__ __forceinline__ void mbar_wait(uint32_t a, uint32_t ph) {
    asm volatile(
        "{\n\t.reg .pred P;\n"
        "WL%=:\n\t"
        "mbarrier.try_wait.parity.acquire.cta.shared::cta.b64 P, [%0], %1, 0x989680;\n\t"
        "@P bra WD%=;\n\t"
        "bra WL%=;\n"
        "WD%=:\n\t}"
        :: "r"(a), "r"(ph) : "memory");
}

#define LDSM4(r, a) \
    asm volatile("ldmatrix.sync.aligned.m8n8.x4.shared.b16 {%0,%1,%2,%3}, [%4];" \
        : "=r"((r)[0]), "=r"((r)[1]), "=r"((r)[2]), "=r"((r)[3]) : "r"(a))

__device__ __forceinline__ void mma16816(float* d, const uint32_t* a, const uint32_t* b) {
    asm volatile("mma.sync.aligned.m16n8k16.row.col.f32.bf16.bf16.f32 "
        "{%0,%1,%2,%3}, {%4,%5,%6,%7}, {%8,%9}, {%0,%1,%2,%3};"
        : "+f"(d[0]), "+f"(d[1]), "+f"(d[2]), "+f"(d[3])
        : "r"(a[0]), "r"(a[1]), "r"(a[2]), "r"(a[3]), "r"(b[0]), "r"(b[1]));
}

__device__ __forceinline__ float sigmf(float x) { return 1.0f / (1.0f + __expf(-x)); }

// ---------------- init: chunked + swizzled weight builds ----------------
__global__ void k_init(const float* __restrict__ W_att, const float* __restrict__ W_ih,
                       const float* __restrict__ W_hh, const float* __restrict__ b_ih,
                       const float* __restrict__ b_hh) {
    long g = (long)blockIdx.x * blockDim.x + threadIdx.x;
    long stride = (long)gridDim.x * blockDim.x;
    for (long i = g; i < (long)NG * KTOT; i += stride) {
        int n = (int)(i / KTOT), k = (int)(i % KTOT);
        int q = n >> 4, r = n & 15;
        int gate = ((r >> 3) << 1) | (r & 1);
        int j = (q << 2) + ((r & 7) >> 1);
        int srow = gate * H_ + j;
        float w = 0.0f;
        if (k < 390)                         w = W_ih[(size_t)srow * 390 + k];
        else if (k >= HOFF && k < HOFF + H_) w = W_hh[(size_t)srow * H_ + (k - HOFF)];
        bf16 hi = __float2bfloat16(w);
        size_t dst = (size_t)(k >> 5) * (NG * 32) + swz(n, k & 31);
        g_Whi[dst] = hi;
        g_Wlo[dst] = __float2bfloat16(w - __bfloat162float(hi));
    }
    for (long i = g; i < (long)NATT * H_; i += stride) {
        int n = (int)(i / H_), k = (int)(i % H_);
        int ks = n >> 7, l = n & 127;
        float w = W_att[(size_t)ks * (H_ * L_) + (size_t)k * L_ + l];
        bf16 hi = __float2bfloat16(w);
        size_t dst = (size_t)(k >> 5) * (NATT * 32) + swz(n, k & 31);
        g_Lhi[dst] = hi;
        g_Llo[dst] = __float2bfloat16(w - __bfloat162float(hi));
    }
    for (long i = g; i < NG; i += stride) {
        int n = (int)i;
        int q = n >> 4, r = n & 15;
        int gate = ((r >> 3) << 1) | (r & 1);
        int j = (q << 2) + ((r & 7) >> 1);
        g_bsum[i] = b_ih[gate * H_ + j] + b_hh[gate * H_ + j];
    }
    bf16 z = __float2bfloat16(0.0f);
    for (long i = g; i < (long)NCHK * B_ * 32; i += stride) {
        g_Ahi0[i] = z; g_Alo0[i] = z; g_Ahi1[i] = z; g_Alo1[i] = z;
    }
    for (long i = g; i < (long)B_ * H_; i += stride) { g_c[i] = 0.0f; g_hmax[i] = -FLT_MAX; }
}

// ---------------- bulk-fed mma.sync GEMM, hi/lo 3-product, fused epilogue ----------------
// Warp tile 32 x WN (WN multiple of 16). 3-stage mbarrier ring fed by cp.async.bulk.
template <int BM, int BN, int WN, bool GATES, int BROWS, int NCH, int CA0>
__global__ void __launch_bounds__((BM / 32) * (BN / WN) * 32, 1)
k_mma(const bf16* __restrict__ gAhi, const bf16* __restrict__ gAlo,
      bf16* __restrict__ wAhi, bf16* __restrict__ wAlo,
      const bf16* __restrict__ gBhi, const bf16* __restrict__ gBlo,
      const float* __restrict__ bias) {
    constexpr int NWX = BN / WN, NWY = BM / 32;
    constexpr int NTHR = NWX * NWY * 32;
    constexpr int NB16 = WN / 16;                 // 16-wide N batches per warp
    constexpr uint32_t STAGE_B = (uint32_t)(BM + BN) * 2u * 64u;
    constexpr uint32_t A_BYTES = (uint32_t)BM * 64u;
    constexpr uint32_t B_BYTES = (uint32_t)BN * 64u;
    constexpr uint32_t TXB = 2u * (A_BYTES + B_BYTES);

    extern __shared__ __align__(128) char dyn[];
    __shared__ __align__(8) uint64_t s_mbar[3];
    __shared__ float s_bias[BN];

    const int tid = threadIdx.x, w = tid >> 5, lane = tid & 31;
    const int wx = w % NWX, wy = w / NWX;
    const int m0 = blockIdx.y * BM, n0 = blockIdx.x * BN;
    const uint32_t smb = smem_u32(dyn);
    const uint32_t mb0 = smem_u32(&s_mbar[0]);

    if (tid == 0) { mbar_init(mb0, 1); mbar_init(mb0 + 8, 1); mbar_init(mb0 + 16, 1); }
    for (int i = tid; i < BN; i += NTHR) s_bias[i] = bias[n0 + i];
    __syncthreads();

    auto issue = [&](int k) {
        uint32_t buf = smb + (uint32_t)(k % 3) * STAGE_B;
        uint32_t mb = mb0 + 8u * (k % 3);
        mbar_expect(mb, TXB);
        const char* srcAh = (const char*)gAhi + ((size_t)(CA0 + k) * B_ + m0) * 64;
        const char* srcAl = (const char*)gAlo + ((size_t)(CA0 + k) * B_ + m0) * 64;
        const char* srcBh = (const char*)gBhi + ((size_t)k * BROWS + n0) * 64;
        const char* srcBl = (const char*)gBlo + ((size_t)k * BROWS + n0) * 64;
        bulk_cp(buf,                         srcAh, A_BYTES, mb);
        bulk_cp(buf + A_BYTES,               srcAl, A_BYTES, mb);
        bulk_cp(buf + 2 * A_BYTES,           srcBh, B_BYTES, mb);
        bulk_cp(buf + 2 * A_BYTES + B_BYTES, srcBl, B_BYTES, mb);
    };
    if (tid == 0) { issue(0); issue(1); }

    float acc[2][WN / 8][4];
#pragma unroll
    for (int i = 0; i < 2; i++)
#pragma unroll
        for (int j = 0; j < WN / 8; j++)
#pragma unroll
            for (int k = 0; k < 4; k++) acc[i][j][k] = 0.0f;

    for (int s = 0; s < NCH; s++) {
        if (tid == 0 && s + 2 < NCH) issue(s + 2);
        mbar_wait(mb0 + 8u * (s % 3), (uint32_t)((s / 3) & 1));

        const uint32_t st  = smb + (uint32_t)(s % 3) * STAGE_B;
        const uint32_t stB = st + 2 * A_BYTES;
#pragma unroll
        for (int ks = 0; ks < 2; ks++) {
            uint32_t ah[2][4], al[2][4];
#pragma unroll
            for (int mt = 0; mt < 2; mt++) {
                int row = wy * 32 + mt * 16 + (lane & 15);
                int seg = (ks * 2 + (lane >> 4)) ^ ((row + (row >> 2)) & 3);
                uint32_t addr = st + (uint32_t)(row * 64 + (seg & 3) * 16);
                LDSM4(ah[mt], addr);
                LDSM4(al[mt], addr + A_BYTES);
            }
#pragma unroll
            for (int nb = 0; nb < NB16; nb++) {
                uint32_t bh[4], bl[4];
                {
                    int gg = lane >> 3;
                    int row = wx * WN + nb * 16 + ((gg >> 1) << 3) + (lane & 7);
                    int seg = (ks * 2 + (gg & 1)) ^ ((row + (row >> 2)) & 3);
                    uint32_t addr = stB + (uint32_t)(row * 64 + (seg & 3) * 16);
                    LDSM4(bh, addr);
                    LDSM4(bl, addr + B_BYTES);
                }
#pragma unroll
                for (int mt = 0; mt < 2; mt++)
#pragma unroll
                    for (int j2 = 0; j2 < 2; j2++) {
                        float* a = acc[mt][nb * 2 + j2];
                        mma16816(a, ah[mt], &bh[j2 * 2]);
                        mma16816(a, ah[mt], &bl[j2 * 2]);
                        mma16816(a, al[mt], &bh[j2 * 2]);
                    }
            }
        }
        __syncthreads();
    }

    const int a_ = lane & 3, rl = lane >> 2;
    if constexpr (GATES) {
#pragma unroll
        for (int mt = 0; mt < 2; mt++)
#pragma unroll
            for (int p = 0; p < WN / 16; p++) {
                const int colb = wx * WN + p * 16;
                const float bi = s_bias[colb + 2 * a_];
                const float bf = s_bias[colb + 2 * a_ + 1];
                const float bg = s_bias[colb + 8 + 2 * a_];
                const float bo = s_bias[colb + 8 + 2 * a_ + 1];
                const int j = ((n0 + colb) >> 2) + a_;
#pragma unroll
                for (int rh = 0; rh < 2; rh++) {
                    float iv = acc[mt][2 * p][2 * rh]     + bi;
                    float fv = acc[mt][2 * p][2 * rh + 1] + bf;
                    float gv = acc[mt][2 * p + 1][2 * rh]     + bg;
                    float ov = acc[mt][2 * p + 1][2 * rh + 1] + bo;
                    int b = m0 + wy * 32 + mt * 16 + rh * 8 + rl;
                    size_t cidx = (size_t)b * H_ + j;
                    float c = sigmf(fv) * g_c[cidx] + sigmf(iv) * tanhf(gv);
                    float h = sigmf(ov) * tanhf(c);
                    g_c[cidx] = c;
                    g_hmax[cidx] = fmaxf(g_hmax[cidx], h);
                    bf16 hh = __float2bfloat16(h);
                    size_t widx = (size_t)(13 + (j >> 5)) * (B_ * 32) + swz(b, j & 31);
                    wAhi[widx] = hh;
                    wAlo[widx] = __float2bfloat16(h - __bfloat162float(hh));
                }
            }
    } else {
#pragma unroll
        for (int mt = 0; mt < 2; mt++)
#pragma unroll
            for (int nt = 0; nt < WN / 8; nt++) {
                const int lc = wx * WN + nt * 8 + 2 * a_;
#pragma unroll
                for (int rh = 0; rh < 2; rh++) {
                    int row = m0 + wy * 32 + mt * 16 + rh * 8 + rl;
                    float2 v;
                    v.x = acc[mt][nt][2 * rh]     + s_bias[lc];
                    v.y = acc[mt][nt][2 * rh + 1] + s_bias[lc + 1];
                    *(float2*)&g_logits[(size_t)row * NATT + n0 + lc] = v;
                }
            }
    }
}

// ---------------- fused softmax + attention pooling (writes v chunked hi/lo) ----------------
__global__ void k_attn(const float* __restrict__ X, bf16* __restrict__ wHi,
                       bf16* __restrict__ wLo) {
    __shared__ float alp[NATT];
    __shared__ float xs[16 * DIN];
    __shared__ float red[16];
    const int b = blockIdx.x;
    const int tid = threadIdx.x;
    for (int i = tid; i < NATT; i += 416) alp[i] = g_logits[b * NATT + i];
    __syncthreads();

    const int wid = tid >> 5, lane = tid & 31;
    float xv = (tid < NATT) ? alp[tid] : -FLT_MAX;
    float m = xv;
#pragma unroll
    for (int off = 16; off; off >>= 1) m = fmaxf(m, __shfl_xor_sync(0xffffffffu, m, off));
    if (lane == 0) red[wid] = m;
    __syncthreads();
    if (tid < NATT) {
        int k4 = (tid >> 7) << 2;
        float rm = fmaxf(fmaxf(red[k4], red[k4 + 1]), fmaxf(red[k4 + 2], red[k4 + 3]));
        xv = expf(xv - rm);
    } else xv = 0.0f;
    __syncthreads();
    float s = xv;
#pragma unroll
    for (int off = 16; off; off >>= 1) s += __shfl_xor_sync(0xffffffffu, s, off);
    if (lane == 0) red[wid] = s;
    __syncthreads();
    if (tid < NATT) {
        int k4 = (tid >> 7) << 2;
        float rs = red[k4] + red[k4 + 1] + red[k4 + 2] + red[k4 + 3];
        alp[tid] = xv / rs;
    }
    __syncthreads();

    float acc = 0.0f;
    const int k = tid / DIN, d = tid - k * DIN;
    const float* Xb = X + (size_t)b * (L_ * DIN);
    for (int lc = 0; lc < L_; lc += 16) {
        for (int i = tid; i < 16 * DIN; i += 416) xs[i] = Xb[lc * DIN + i];
        __syncthreads();
        if (tid < 390) {
#pragma unroll
            for (int l = 0; l < 16; l++) acc += alp[k * L_ + lc + l] * xs[l * DIN + d];
        }
        __syncthreads();
    }
    if (tid < 390) {
        bf16 hi = __float2bfloat16(acc);
        size_t off = (size_t)(tid >> 5) * (B_ * 32) + swz(b, tid & 31);
        wHi[off] = hi;
        wLo[off] = __float2bfloat16(acc - __bfloat162float(hi));
    }
}

// ---------------- fused tail ----------------
__global__ void k_tail(const float* __restrict__ Fe, const float* __restrict__ W_d1,
                       const float* __restrict__ b_d1, const float* __restrict__ W_r,
                       const float* __restrict__ b_r, const float* __restrict__ W_a,
                       const float* __restrict__ W_d2, const float* __restrict__ b_d2,
                       float* __restrict__ out) {
    __shared__ float hs[H_];
    __shared__ float yb[FEAT_];
    __shared__ float r1[PROJ_], r2[PROJ_], sb[PROJ_];
    __shared__ float aw[2];
    const int b = blockIdx.x, tid = threadIdx.x;   // 64 threads
    for (int i = tid; i < H_; i += 64) hs[i] = g_hmax[(size_t)b * H_ + i];
    __syncthreads();
    if (tid < FEAT_) {
        float a = b_d1[tid];
        const float* w = W_d1 + tid * H_;
        for (int k2 = 0; k2 < H_; k2++) a += hs[k2] * w[k2];
        yb[tid] = fmaxf(a, 0.0f);
    }
    __syncthreads();
    if (tid < PROJ_) {
        float a = b_r[tid], a2 = b_r[tid];
        const float* w = W_r + tid * FEAT_;
        const float* fe = Fe + b * FEAT_;
        for (int q = 0; q < FEAT_; q++) { a += yb[q] * w[q]; a2 += fe[q] * w[q]; }
        r1[tid] = a  > 0.0f ? a  : 0.01f * a;
        r2[tid] = a2 > 0.0f ? a2 : 0.01f * a2;
    }
    __syncthreads();
    if (tid == 0) {
        float s1 = 0.0f, s2 = 0.0f;
        for (int p = 0; p < PROJ_; p++) { s1 += tanhf(r1[p]) * W_a[p]; s2 += tanhf(r2[p]) * W_a[p]; }
        float mx = fmaxf(s1, s2);
        float e1 = expf(s1 - mx), e2 = expf(s2 - mx);
        float inv = 1.0f / (e1 + e2);
        aw[0] = e1 * inv; aw[1] = e2 * inv;
    }
    __syncthreads();
    if (tid < PROJ_) sb[tid] = fmaxf(aw[0] * r1[tid] + aw[1] * r2[tid], 0.0f);
    __syncthreads();
    if (tid < 2) {
        float a = b_d2[tid];
        const float* w = W_d2 + tid * PROJ_;
        for (int p = 0; p < PROJ_; p++) a += sb[p] * w[p];
        out[b * 2 + tid] = a;
    }
}

// ---------------- launch ----------------
extern "C" void kernel_launch(void* const* d_in, const int* in_sizes, int n_in,
                              void* d_out, int out_size) {
    const float* X     = (const float*)d_in[0];
    const float* Fe    = (const float*)d_in[1];
    const float* W_att = (const float*)d_in[2];
    const float* b_att = (const float*)d_in[3];
    const float* W_ih  = (const float*)d_in[4];
    const float* W_hh  = (const float*)d_in[5];
    const float* b_ih  = (const float*)d_in[6];
    const float* b_hh  = (const float*)d_in[7];
    const float* W_d1  = (const float*)d_in[8];
    const float* b_d1  = (const float*)d_in[9];
    const float* W_r   = (const float*)d_in[10];
    const float* b_r   = (const float*)d_in[11];
    const float* W_a   = (const float*)d_in[12];
    const float* W_d2  = (const float*)d_in[13];
    const float* b_d2  = (const float*)d_in[14];
    float* out = (float*)d_out;

    bf16 *Ah0, *Al0, *Ah1, *Al1, *Whi, *Wlo, *Lhi, *Llo;
    float *bsum;
    cudaGetSymbolAddress((void**)&Ah0, g_Ahi0);
    cudaGetSymbolAddress((void**)&Al0, g_Alo0);
    cudaGetSymbolAddress((void**)&Ah1, g_Ahi1);
    cudaGetSymbolAddress((void**)&Al1, g_Alo1);
    cudaGetSymbolAddress((void**)&Whi, g_Whi);
    cudaGetSymbolAddress((void**)&Wlo, g_Wlo);
    cudaGetSymbolAddress((void**)&Lhi, g_Lhi);
    cudaGetSymbolAddress((void**)&Llo, g_Llo);
    cudaGetSymbolAddress((void**)&bsum, g_bsum);

    constexpr int DSMEM_G = 3 * (128 + 192) * 2 * 64;   // 122880 B
    constexpr int DSMEM_L = 3 * (64 + 64) * 2 * 64;     //  49152 B
    cudaFuncSetAttribute((const void*)k_mma<128, 192, 48, true,  NG,   37, 0>,
                         cudaFuncAttributeMaxDynamicSharedMemorySize, DSMEM_G);
    cudaFuncSetAttribute((const void*)k_mma<64, 64, 16, false, NATT, 24, 13>,
                         cudaFuncAttributeMaxDynamicSharedMemorySize, DSMEM_L);

    k_init<<<2048, 256>>>(W_att, W_ih, W_hh, b_ih, b_hh);

    for (int t = 0; t < L_; t++) {
        bf16* rdHi = (t & 1) ? Ah1 : Ah0;
        bf16* rdLo = (t & 1) ? Al1 : Al0;
        bf16* wrHi = (t & 1) ? Ah0 : Ah1;
        bf16* wrLo = (t & 1) ? Al0 : Al1;
        // logits[1024,384] = h @ Wl + b_att   (A chunks 13..36), 8 warps, grid 96
        k_mma<64, 64, 16, false, NATT, 24, 13><<<dim3(NATT / 64, B_ / 64), 256, DSMEM_L>>>(
            rdHi, rdLo, nullptr, nullptr, Lhi, Llo, b_att);
        // softmax + attention pooling -> v chunks 0..12 of rd buffer
        k_attn<<<B_, 416>>>(X, rdHi, rdLo);
        // gates = [v|h] @ Wcat + bsum, fused LSTM cell -> h, 16 warps, grid 128 (1 wave)
        k_mma<128, 192, 48, true, NG, 37, 0><<<dim3(NG / 192, B_ / 128), 512, DSMEM_G>>>(
            rdHi, rdLo, wrHi, wrLo, Whi, Wlo, bsum);
    }

    k_tail<<<B_, 64>>>(Fe, W_d1, b_d1, W_r, b_r, W_a, W_d2, b_d2, out);
}